// round 11
// baseline (speedup 1.0000x reference)
#include <cuda_runtime.h>
#include <cuda_bf16.h>
#include <cstdint>

// Problem constants
#define S      2048
#define E      2048
#define HQ     32
#define HKV    8
#define D      64
#define QSTRIDE (HQ*D)    // 2048
#define KSTRIDE (HKV*D)   // 512
#define NTOT   (QSTRIDE + 2*KSTRIDE)  // 3072

// ---------------- scratch (device globals; no allocation allowed) ----------
__device__ float g_Q[S * QSTRIDE];
__device__ float g_K[S * KSTRIDE];
__device__ float g_V[S * KSTRIDE];
__device__ float g_A[S * QSTRIDE];

// ---------------- helpers ---------------------------------------------------
__device__ __forceinline__ unsigned f2t(float f) {
    unsigned u;
    asm("cvt.rna.tf32.f32 %0, %1;" : "=r"(u) : "f"(f));
    return u;
}

__device__ __forceinline__ void mma_tf32(float c[4],
                                         unsigned a0, unsigned a1, unsigned a2, unsigned a3,
                                         unsigned b0, unsigned b1) {
    asm volatile(
        "mma.sync.aligned.m16n8k8.row.col.f32.tf32.tf32.f32 "
        "{%0,%1,%2,%3}, {%4,%5,%6,%7}, {%8,%9}, {%0,%1,%2,%3};\n"
        : "+f"(c[0]), "+f"(c[1]), "+f"(c[2]), "+f"(c[3])
        : "r"(a0), "r"(a1), "r"(a2), "r"(a3), "r"(b0), "r"(b1));
}

__device__ __forceinline__ void mma_bf16(float c[4],
                                         unsigned a0, unsigned a1, unsigned a2, unsigned a3,
                                         unsigned b0, unsigned b1) {
    asm volatile(
        "mma.sync.aligned.m16n8k16.row.col.f32.bf16.bf16.f32 "
        "{%0,%1,%2,%3}, {%4,%5,%6,%7}, {%8,%9}, {%0,%1,%2,%3};\n"
        : "+f"(c[0]), "+f"(c[1]), "+f"(c[2]), "+f"(c[3])
        : "r"(a0), "r"(a1), "r"(a2), "r"(a3), "r"(b0), "r"(b1));
}

// bf16 hi/lo pair packing: pair = (x in low half, y in high half)
__device__ __forceinline__ unsigned pack_hi2(float x, float y) {
    return __byte_perm(__float_as_uint(x), __float_as_uint(y), 0x7632);
}
__device__ __forceinline__ unsigned pack_lo2(float x, float y) {
    float rx = x - __uint_as_float(__float_as_uint(x) & 0xffff0000u);
    float ry = y - __uint_as_float(__float_as_uint(y) & 0xffff0000u);
    unsigned d;
    asm("cvt.rn.bf16x2.f32 %0, %1, %2;" : "=r"(d) : "f"(ry), "f"(rx));
    return d;
}

// GEMM smem geometry: A row-major [128][36], B [32][136], double buffered.
#define AP   36
#define BP   136
#define ASZ  (128 * AP)
#define BSZ  (32 * BP)
#define GEMM_SMEM_BYTES ((2 * ASZ + 2 * BSZ) * 4)   // 71680

// ============================================================================
// GEMM core (stable R5 design, untouched).
// ============================================================================
struct GemmCore {
    template <bool ROPE_EPI>
    static __device__ __forceinline__ void run(
        const float* __restrict__ A, const float* __restrict__ B,
        float* __restrict__ C, const float* __restrict__ F,
        int N, int K, int mbase, int nbase_local) {

        extern __shared__ unsigned smg[];
        unsigned* AsBuf = smg;
        unsigned* BsBuf = smg + 2 * ASZ;

        const int tid  = threadIdx.x;
        const int lane = tid & 31;
        const int warp = tid >> 5;
        const int m0w = (warp >> 1) * 64;
        const int n0w = (warp & 1) * 64;
        const int qr = lane >> 2, qc = lane & 3;

        float acc[4][8][4];
#pragma unroll
        for (int mt = 0; mt < 4; ++mt)
#pragma unroll
            for (int nt = 0; nt < 8; ++nt)
#pragma unroll
                for (int j = 0; j < 4; ++j) acc[mt][nt][j] = 0.f;

        const int arow = tid >> 3, af4 = tid & 7;
        const int brow = tid >> 5, bf4 = tid & 31;

        float4 pa[8], pb[8];

#pragma unroll
        for (int i = 0; i < 8; ++i)
            pa[i] = *(const float4*)&A[(size_t)(mbase + arow + i * 16) * K + af4 * 4];
#pragma unroll
        for (int i = 0; i < 8; ++i)
            pb[i] = *(const float4*)&B[(size_t)(brow + i * 4) * N + nbase_local + bf4 * 4];
#pragma unroll
        for (int i = 0; i < 8; ++i) {
            int r = arow + i * 16;
            uint4 u = make_uint4(f2t(pa[i].x), f2t(pa[i].y), f2t(pa[i].z), f2t(pa[i].w));
            *(uint4*)&AsBuf[r * AP + af4 * 4] = u;
        }
#pragma unroll
        for (int i = 0; i < 8; ++i) {
            int r = brow + i * 4;
            uint4 u = make_uint4(f2t(pb[i].x), f2t(pb[i].y), f2t(pb[i].z), f2t(pb[i].w));
            *(uint4*)&BsBuf[r * BP + bf4 * 4] = u;
        }
        if (32 < K) {
#pragma unroll
            for (int i = 0; i < 8; ++i)
                pa[i] = *(const float4*)&A[(size_t)(mbase + arow + i * 16) * K + 32 + af4 * 4];
#pragma unroll
            for (int i = 0; i < 8; ++i)
                pb[i] = *(const float4*)&B[(size_t)(32 + brow + i * 4) * N + nbase_local + bf4 * 4];
        }
        __syncthreads();

        int buf = 0;
        for (int kb = 0; kb < K; kb += 32) {
            unsigned* Asb = AsBuf + buf * ASZ;
            unsigned* Bsb = BsBuf + buf * BSZ;

            if (kb + 32 < K) {
                unsigned* Asn = AsBuf + (buf ^ 1) * ASZ;
                unsigned* Bsn = BsBuf + (buf ^ 1) * BSZ;
#pragma unroll
                for (int i = 0; i < 8; ++i) {
                    int r = arow + i * 16;
                    uint4 u = make_uint4(f2t(pa[i].x), f2t(pa[i].y), f2t(pa[i].z), f2t(pa[i].w));
                    *(uint4*)&Asn[r * AP + af4 * 4] = u;
                }
#pragma unroll
                for (int i = 0; i < 8; ++i) {
                    int r = brow + i * 4;
                    uint4 u = make_uint4(f2t(pb[i].x), f2t(pb[i].y), f2t(pb[i].z), f2t(pb[i].w));
                    *(uint4*)&Bsn[r * BP + bf4 * 4] = u;
                }
            }
            if (kb + 64 < K) {
#pragma unroll
                for (int i = 0; i < 8; ++i)
                    pa[i] = *(const float4*)&A[(size_t)(mbase + arow + i * 16) * K + kb + 64 + af4 * 4];
#pragma unroll
                for (int i = 0; i < 8; ++i)
                    pb[i] = *(const float4*)&B[(size_t)(kb + 64 + brow + i * 4) * N + nbase_local + bf4 * 4];
            }

#pragma unroll
            for (int ks = 0; ks < 4; ++ks) {
                const int k0 = ks * 8;
                unsigned a[4][4];
#pragma unroll
                for (int mt = 0; mt < 4; ++mt) {
                    int m = m0w + mt * 16;
                    a[mt][0] = Asb[(m + qr) * AP + k0 + qc];
                    a[mt][1] = Asb[(m + 8 + qr) * AP + k0 + qc];
                    a[mt][2] = Asb[(m + qr) * AP + k0 + 4 + qc];
                    a[mt][3] = Asb[(m + 8 + qr) * AP + k0 + 4 + qc];
                }
#pragma unroll
                for (int nt = 0; nt < 8; ++nt) {
                    int n = n0w + nt * 8;
                    unsigned b0 = Bsb[(k0 + qc) * BP + n + qr];
                    unsigned b1 = Bsb[(k0 + 4 + qc) * BP + n + qr];
#pragma unroll
                    for (int mt = 0; mt < 4; ++mt)
                        mma_tf32(acc[mt][nt], a[mt][0], a[mt][1], a[mt][2], a[mt][3], b0, b1);
                }
            }
            __syncthreads();
            buf ^= 1;
        }

#pragma unroll
        for (int mt = 0; mt < 4; ++mt) {
#pragma unroll
            for (int nt = 0; nt < 8; ++nt) {
                int row = mbase + m0w + mt * 16 + qr;
                int lcol = nbase_local + n0w + nt * 8 + 2 * qc;
                float2 v0 = make_float2(acc[mt][nt][0], acc[mt][nt][1]);
                float2 v1 = make_float2(acc[mt][nt][2], acc[mt][nt][3]);
                if (ROPE_EPI) {
                    int d = lcol & 63;
                    float2 f0 = *(const float2*)&F[(size_t)row * 64 + d];
                    float2 f1 = *(const float2*)&F[(size_t)(row + 8) * 64 + d];
                    v0 = make_float2(v0.x * f0.x - v0.y * f0.y, v0.x * f0.y + v0.y * f0.x);
                    v1 = make_float2(v1.x * f1.x - v1.y * f1.y, v1.x * f1.y + v1.y * f1.x);
                }
                *(float2*)&C[(size_t)row * N + lcol] = v0;
                *(float2*)&C[(size_t)(row + 8) * N + lcol] = v1;
            }
        }
    }
};

__global__ __launch_bounds__(128)
void qkv_gemm_kernel(const float* __restrict__ A,
                     const float* __restrict__ Wq,
                     const float* __restrict__ Wk,
                     const float* __restrict__ Wv,
                     const float* __restrict__ F,
                     float* __restrict__ Qp,
                     float* __restrict__ Kp,
                     float* __restrict__ Vp) {
    const int mbase = blockIdx.y * 128;
    const int nbase = blockIdx.x * 128;
    if (nbase < QSTRIDE) {
        GemmCore::run<true>(A, Wq, Qp, F, QSTRIDE, E, mbase, nbase);
    } else if (nbase < QSTRIDE + KSTRIDE) {
        GemmCore::run<true>(A, Wk, Kp, F, KSTRIDE, E, mbase, nbase - QSTRIDE);
    } else {
        GemmCore::run<false>(A, Wv, Vp, nullptr, KSTRIDE, E, mbase,
                             nbase - QSTRIDE - KSTRIDE);
    }
}

__global__ __launch_bounds__(128)
void tgemm_kernel(const float* __restrict__ A,
                  const float* __restrict__ B,
                  float* __restrict__ C,
                  int M, int N, int K) {
    GemmCore::run<false>(A, B, C, nullptr, N, K, blockIdx.y * 128, blockIdx.x * 128);
}

// ============================================================================
// Flash attention v2: q-tile 64, 128 threads (warps 0-1 consumers / 32 rows
// each; warps 2-3 producers). K tf32 k-major; V bf16 hi/lo n-major pairs.
// P·V via register fragments (bf16 3-term split) — no P smem round trip.
// 89 KB smem -> 2 CTAs/SM.
// ============================================================================
#define FPQ 68            // Q/K pitch (words)
#define VP  36            // V pitch (pairs)
#define QW  (64 * FPQ)    // Q words
#define KW  (64 * FPQ)    // K buffer words
#define VW  (64 * VP)     // V hi (or lo) buffer words
#define FA_SMEM_WORDS (QW + 2*KW + 2*(2*VW))
#define FA_SMEM_BYTES (FA_SMEM_WORDS * 4)   // 89088

__global__ __launch_bounds__(128)
void flash_v2_kernel(const float* __restrict__ Q,
                     const float* __restrict__ Kg,
                     const float* __restrict__ Vg,
                     float* __restrict__ O) {
    const int h = blockIdx.y;
    const int qt = (gridDim.x - 1) - blockIdx.x;   // heavy tiles first
    const int qbase = qt * 64;
    const int kh = h >> 2;

    extern __shared__ unsigned smu[];
    unsigned* Qs  = smu;                   // [64][FPQ]
    unsigned* Ks0 = Qs + QW;               // 2 x [64][FPQ]
    unsigned* Vh0 = Ks0 + 2 * KW;          // 2 x [64][VP]  (bf16x2 hi pairs)
    unsigned* Vl0 = Vh0 + 2 * VW;          // 2 x [64][VP]  (bf16x2 lo pairs)

    const int tid = threadIdx.x;
    const int lane = tid & 31;
    const int warp = tid >> 5;

    // ---- Q load (all 128 threads): 64 rows x 16 f4 ----
    {
        const int f4 = tid & 15;
        const int row0 = tid >> 4;    // 0..7
#pragma unroll
        for (int i = 0; i < 8; ++i) {
            int r = row0 + i * 8;
            float4 v = *(const float4*)&Q[(size_t)(qbase + r) * QSTRIDE + h * D + f4 * 4];
            uint4 u = make_uint4(f2t(v.x), f2t(v.y), f2t(v.z), f2t(v.w));
            *(uint4*)&Qs[r * FPQ + f4 * 4] = u;
        }
    }

    if (warp >= 2) {
        // ======================= PRODUCER ====================================
        const int ptid = tid - 64;        // 0..63
        const int kf4 = ptid & 15;        // K: col group
        const int krow0 = ptid >> 4;      // K: 0..3
        const int vf4 = ptid & 15;        // V: n group (4 cols)
        const int vkp0 = ptid >> 4;       // V: 0..3

#define PROD_FILL(KT, KSB, VHB, VLB) do {                                       \
    const int kb_ = (KT) * 64;                                                  \
    _Pragma("unroll")                                                           \
    for (int i_ = 0; i_ < 16; ++i_) {                                           \
        int r_ = krow0 + i_ * 4;                                                \
        float4 v_ = *(const float4*)&Kg[(size_t)(kb_ + r_) * KSTRIDE            \
                                        + kh * D + kf4 * 4];                    \
        uint4 u_ = make_uint4(f2t(v_.x), f2t(v_.y), f2t(v_.z), f2t(v_.w));      \
        *(uint4*)&(KSB)[r_ * FPQ + kf4 * 4] = u_;                               \
    }                                                                           \
    _Pragma("unroll")                                                           \
    for (int i_ = 0; i_ < 8; ++i_) {                                            \
        int kp_ = vkp0 + i_ * 4;          /* seq pair 0..31 */                   \
        float4 va_ = *(const float4*)&Vg[(size_t)(kb_ + 2 * kp_) * KSTRIDE      \
                                         + kh * D + vf4 * 4];                   \
        float4 vb_ = *(const float4*)&Vg[(size_t)(kb_ + 2 * kp_ + 1) * KSTRIDE  \
                                         + kh * D + vf4 * 4];                   \
        (VHB)[(vf4 * 4 + 0) * VP + kp_] = pack_hi2(va_.x, vb_.x);               \
        (VHB)[(vf4 * 4 + 1) * VP + kp_] = pack_hi2(va_.y, vb_.y);               \
        (VHB)[(vf4 * 4 + 2) * VP + kp_] = pack_hi2(va_.z, vb_.z);               \
        (VHB)[(vf4 * 4 + 3) * VP + kp_] = pack_hi2(va_.w, vb_.w);               \
        (VLB)[(vf4 * 4 + 0) * VP + kp_] = pack_lo2(va_.x, vb_.x);               \
        (VLB)[(vf4 * 4 + 1) * VP + kp_] = pack_lo2(va_.y, vb_.y);               \
        (VLB)[(vf4 * 4 + 2) * VP + kp_] = pack_lo2(va_.z, vb_.z);               \
        (VLB)[(vf4 * 4 + 3) * VP + kp_] = pack_lo2(va_.w, vb_.w);               \
    }                                                                           \
} while (0)

        PROD_FILL(0, Ks0, Vh0, Vl0);
        __syncthreads();   // tile 0 ready
        for (int kt = 0; kt <= qt; ++kt) {
            if (kt < qt) {
                const int p1 = (kt + 1) & 1;
                PROD_FILL(kt + 1, Ks0 + p1 * KW, Vh0 + p1 * VW, Vl0 + p1 * VW);
            }
            __syncthreads();
        }
#undef PROD_FILL
        return;
    }

    // ======================= CONSUMER ========================================
    const int m0 = warp * 32;
    const int qr = lane >> 2;
    const int qc = lane & 3;

    float o[2][8][4];
#pragma unroll
    for (int mt = 0; mt < 2; ++mt)
#pragma unroll
        for (int nt = 0; nt < 8; ++nt)
#pragma unroll
            for (int j = 0; j < 4; ++j) o[mt][nt][j] = 0.f;
    float mr[2][2], lr[2][2];
#pragma unroll
    for (int mt = 0; mt < 2; ++mt) {
        mr[mt][0] = -1e30f; mr[mt][1] = -1e30f;
        lr[mt][0] = 0.f;    lr[mt][1] = 0.f;
    }

    __syncthreads();   // tile 0 ready

    for (int kt = 0; kt <= qt; ++kt) {
        const int kbase = kt * 64;
        const int p = kt & 1;
        unsigned* Ksb = Ks0 + p * KW;
        unsigned* Vhb = Vh0 + p * VW;
        unsigned* Vlb = Vl0 + p * VW;

        // ---- S = Q K^T (tf32) ----
        float s[2][8][4];
#pragma unroll
        for (int mt = 0; mt < 2; ++mt)
#pragma unroll
            for (int nt = 0; nt < 8; ++nt)
#pragma unroll
                for (int j = 0; j < 4; ++j) s[mt][nt][j] = 0.f;

#pragma unroll
        for (int ks = 0; ks < 8; ++ks) {
            const int k0 = ks * 8;
            unsigned a[2][4];
#pragma unroll
            for (int mt = 0; mt < 2; ++mt) {
                int m = m0 + mt * 16;
                a[mt][0] = Qs[(m + qr) * FPQ + k0 + qc];
                a[mt][1] = Qs[(m + 8 + qr) * FPQ + k0 + qc];
                a[mt][2] = Qs[(m + qr) * FPQ + k0 + 4 + qc];
                a[mt][3] = Qs[(m + 8 + qr) * FPQ + k0 + 4 + qc];
            }
#pragma unroll
            for (int nt = 0; nt < 8; ++nt) {
                unsigned b0 = Ksb[(nt * 8 + qr) * FPQ + k0 + qc];
                unsigned b1 = Ksb[(nt * 8 + qr) * FPQ + k0 + 4 + qc];
#pragma unroll
                for (int mt = 0; mt < 2; ++mt)
                    mma_tf32(s[mt][nt], a[mt][0], a[mt][1], a[mt][2], a[mt][3], b0, b1);
            }
        }

        // ---- scale + causal mask + online softmax (per mt) ----
        const bool diag = (kt == qt);
#pragma unroll
        for (int mt = 0; mt < 2; ++mt) {
            const int q_lo = qbase + m0 + mt * 16 + qr;
            const int q_hi = q_lo + 8;
#pragma unroll
            for (int nt = 0; nt < 8; ++nt) {
#pragma unroll
                for (int j = 0; j < 2; ++j) {
                    int kcol = kbase + nt * 8 + 2 * qc + j;
                    float v0 = s[mt][nt][j] * 0.125f;
                    float v1 = s[mt][nt][2 + j] * 0.125f;
                    if (diag && kcol > q_lo) v0 = -1e30f;
                    if (diag && kcol > q_hi) v1 = -1e30f;
                    s[mt][nt][j] = v0;
                    s[mt][nt][2 + j] = v1;
                }
            }

            float tm_lo = -1e30f, tm_hi = -1e30f;
#pragma unroll
            for (int nt = 0; nt < 8; ++nt) {
                tm_lo = fmaxf(tm_lo, fmaxf(s[mt][nt][0], s[mt][nt][1]));
                tm_hi = fmaxf(tm_hi, fmaxf(s[mt][nt][2], s[mt][nt][3]));
            }
#pragma unroll
            for (int off = 1; off <= 2; off <<= 1) {
                tm_lo = fmaxf(tm_lo, __shfl_xor_sync(0xffffffffu, tm_lo, off));
                tm_hi = fmaxf(tm_hi, __shfl_xor_sync(0xffffffffu, tm_hi, off));
            }
            float mn_lo = fmaxf(mr[mt][0], tm_lo);
            float mn_hi = fmaxf(mr[mt][1], tm_hi);
            float fac_lo = __expf(mr[mt][0] - mn_lo);
            float fac_hi = __expf(mr[mt][1] - mn_hi);

            float sum_lo = 0.f, sum_hi = 0.f;
#pragma unroll
            for (int nt = 0; nt < 8; ++nt) {
                float p0 = __expf(s[mt][nt][0] - mn_lo);
                float p1 = __expf(s[mt][nt][1] - mn_lo);
                float p2 = __expf(s[mt][nt][2] - mn_hi);
                float p3 = __expf(s[mt][nt][3] - mn_hi);
                s[mt][nt][0] = p0; s[mt][nt][1] = p1;
                s[mt][nt][2] = p2; s[mt][nt][3] = p3;
                sum_lo += p0 + p1;
                sum_hi += p2 + p3;
            }
#pragma unroll
            for (int off = 1; off <= 2; off <<= 1) {
                sum_lo += __shfl_xor_sync(0xffffffffu, sum_lo, off);
                sum_hi += __shfl_xor_sync(0xffffffffu, sum_hi, off);
            }
            lr[mt][0] = lr[mt][0] * fac_lo + sum_lo;
            lr[mt][1] = lr[mt][1] * fac_hi + sum_hi;
            mr[mt][0] = mn_lo;
            mr[mt][1] = mn_hi;

#pragma unroll
            for (int nt = 0; nt < 8; ++nt) {
                o[mt][nt][0] *= fac_lo; o[mt][nt][1] *= fac_lo;
                o[mt][nt][2] *= fac_hi; o[mt][nt][3] *= fac_hi;
            }
        }

        // ---- O += P V : bf16 register fragments, 3-term hi/lo split ----
#pragma unroll
        for (int c = 0; c < 4; ++c) {
            unsigned ah[2][4], al[2][4];
#pragma unroll
            for (int mt = 0; mt < 2; ++mt) {
                ah[mt][0] = pack_hi2(s[mt][2*c][0],   s[mt][2*c][1]);
                ah[mt][1] = pack_hi2(s[mt][2*c][2],   s[mt][2*c][3]);
                ah[mt][2] = pack_hi2(s[mt][2*c+1][0], s[mt][2*c+1][1]);
                ah[mt][3] = pack_hi2(s[mt][2*c+1][2], s[mt][2*c+1][3]);
                al[mt][0] = pack_lo2(s[mt][2*c][0],   s[mt][2*c][1]);
                al[mt][1] = pack_lo2(s[mt][2*c][2],   s[mt][2*c][3]);
                al[mt][2] = pack_lo2(s[mt][2*c+1][0], s[mt][2*c+1][1]);
                al[mt][3] = pack_lo2(s[mt][2*c+1][2], s[mt][2*c+1][3]);
            }
#pragma unroll
            for (int nt = 0; nt < 8; ++nt) {
                const int vrow = (nt * 8 + qr) * VP;
                unsigned bh0 = Vhb[vrow + 8*c + qc];
                unsigned bh1 = Vhb[vrow + 8*c + 4 + qc];
                unsigned bl0 = Vlb[vrow + 8*c + qc];
                unsigned bl1 = Vlb[vrow + 8*c + 4 + qc];
#pragma unroll
                for (int mt = 0; mt < 2; ++mt) {
                    mma_bf16(o[mt][nt], ah[mt][0], ah[mt][1], ah[mt][2], ah[mt][3], bh0, bh1);
                    mma_bf16(o[mt][nt], al[mt][0], al[mt][1], al[mt][2], al[mt][3], bh0, bh1);
                    mma_bf16(o[mt][nt], ah[mt][0], ah[mt][1], ah[mt][2], ah[mt][3], bl0, bl1);
                }
            }
        }

        __syncthreads();
    }

    // ---- normalize + write out ----
#pragma unroll
    for (int mt = 0; mt < 2; ++mt) {
        float inv_lo = 1.f / lr[mt][0];
        float inv_hi = 1.f / lr[mt][1];
#pragma unroll
        for (int nt = 0; nt < 8; ++nt) {
            int row = qbase + m0 + mt * 16 + qr;
            int col = h * D + nt * 8 + 2 * qc;
            *(float2*)&O[(size_t)row * QSTRIDE + col] =
                make_float2(o[mt][nt][0] * inv_lo, o[mt][nt][1] * inv_lo);
            *(float2*)&O[(size_t)(row + 8) * QSTRIDE + col] =
                make_float2(o[mt][nt][2] * inv_hi, o[mt][nt][3] * inv_hi);
        }
    }
}

// ---------------- launch ---------------------------------------------------
extern "C" void kernel_launch(void* const* d_in, const int* in_sizes, int n_in,
                              void* d_out, int out_size) {
    const float* x  = (const float*)d_in[0];
    const float* fc = (const float*)d_in[1];
    const float* Wq = (const float*)d_in[3];
    const float* Wk = (const float*)d_in[4];
    const float* Wv = (const float*)d_in[5];
    const float* Wo = (const float*)d_in[6];
    float* out = (float*)d_out;

    float *Q, *K, *V, *A;
    cudaGetSymbolAddress((void**)&Q, g_Q);
    cudaGetSymbolAddress((void**)&K, g_K);
    cudaGetSymbolAddress((void**)&V, g_V);
    cudaGetSymbolAddress((void**)&A, g_A);

    cudaFuncSetAttribute(qkv_gemm_kernel,
                         cudaFuncAttributeMaxDynamicSharedMemorySize, GEMM_SMEM_BYTES);
    cudaFuncSetAttribute(tgemm_kernel,
                         cudaFuncAttributeMaxDynamicSharedMemorySize, GEMM_SMEM_BYTES);
    cudaFuncSetAttribute(flash_v2_kernel,
                         cudaFuncAttributeMaxDynamicSharedMemorySize, FA_SMEM_BYTES);

    // fused QKV projection + RoPE (Q,K only)
    qkv_gemm_kernel<<<dim3(NTOT / 128, S / 128), 128, GEMM_SMEM_BYTES>>>(
        x, Wq, Wk, Wv, fc, Q, K, V);

    // causal GQA flash attention v2
    flash_v2_kernel<<<dim3(S / 64, HQ), 128, FA_SMEM_BYTES>>>(Q, K, V, A);

    // output projection
    tgemm_kernel<<<dim3(E / 128, S / 128), 128, GEMM_SMEM_BYTES>>>(A, Wo, out, S, E, E);
}

// round 12
// speedup vs baseline: 1.1067x; 1.1067x over previous
#include <cuda_runtime.h>
#include <cuda_bf16.h>
#include <cstdint>

// Problem constants
#define S      2048
#define E      2048
#define HQ     32
#define HKV    8
#define D      64
#define QSTRIDE (HQ*D)    // 2048
#define KSTRIDE (HKV*D)   // 512
#define NTOT   (QSTRIDE + 2*KSTRIDE)  // 3072

// ---------------- scratch (device globals; no allocation allowed) ----------
__device__ float g_Q[S * QSTRIDE];
__device__ float g_K[S * KSTRIDE];
__device__ float g_V[S * KSTRIDE];
__device__ float g_A[S * QSTRIDE];

// ---------------- helpers ---------------------------------------------------
__device__ __forceinline__ unsigned f2t(float f) {
    unsigned u;
    asm("cvt.rna.tf32.f32 %0, %1;" : "=r"(u) : "f"(f));
    return u;
}

__device__ __forceinline__ void mma_tf32(float c[4],
                                         unsigned a0, unsigned a1, unsigned a2, unsigned a3,
                                         unsigned b0, unsigned b1) {
    asm volatile(
        "mma.sync.aligned.m16n8k8.row.col.f32.tf32.tf32.f32 "
        "{%0,%1,%2,%3}, {%4,%5,%6,%7}, {%8,%9}, {%0,%1,%2,%3};\n"
        : "+f"(c[0]), "+f"(c[1]), "+f"(c[2]), "+f"(c[3])
        : "r"(a0), "r"(a1), "r"(a2), "r"(a3), "r"(b0), "r"(b1));
}

// GEMM smem geometry: A row-major [128][36], B [32][264], double buffered.
#define AP   36
#define BP2  264
#define ASZ  (128 * AP)        // 4608 words
#define BSZ2 (32 * BP2)        // 8448 words
#define GEMM_SMEM_BYTES ((2 * ASZ + 2 * BSZ2) * 4)   // 104448

// ============================================================================
// GEMM core v2: 256 threads / 8 warps (2x4), block 128x256, warp tile 64x64
// (mt=4, nt=8), BK=32, register-prefetch double-buffered smem, tf32 at store.
// ============================================================================
struct GemmCore {
    template <bool ROPE_EPI>
    static __device__ __forceinline__ void run(
        const float* __restrict__ A, const float* __restrict__ B,
        float* __restrict__ C, const float* __restrict__ F,
        int N, int K, int mbase, int nbase_local) {

        extern __shared__ unsigned smg[];
        unsigned* AsBuf = smg;                 // 2 * ASZ
        unsigned* BsBuf = smg + 2 * ASZ;       // 2 * BSZ2

        const int tid  = threadIdx.x;
        const int lane = tid & 31;
        const int warp = tid >> 5;             // 0..7
        const int m0w = (warp >> 2) * 64;      // 0,64
        const int n0w = (warp & 3) * 64;       // 0,64,128,192
        const int qr = lane >> 2, qc = lane & 3;

        float acc[4][8][4];
#pragma unroll
        for (int mt = 0; mt < 4; ++mt)
#pragma unroll
            for (int nt = 0; nt < 8; ++nt)
#pragma unroll
                for (int j = 0; j < 4; ++j) acc[mt][nt][j] = 0.f;

        const int arow = tid >> 3, af4 = tid & 7;    // A: 32 rows/pass x 8 f4
        const int brow = tid >> 6, bf4 = tid & 63;   // B: 4 rows/pass x 64 f4

        float4 pa[4], pb[8];

        // ---- prologue: block 0 -> buf0, prefetch block 1 ----
#pragma unroll
        for (int i = 0; i < 4; ++i)
            pa[i] = *(const float4*)&A[(size_t)(mbase + arow + i * 32) * K + af4 * 4];
#pragma unroll
        for (int i = 0; i < 8; ++i)
            pb[i] = *(const float4*)&B[(size_t)(brow + i * 4) * N + nbase_local + bf4 * 4];
#pragma unroll
        for (int i = 0; i < 4; ++i) {
            int r = arow + i * 32;
            uint4 u = make_uint4(f2t(pa[i].x), f2t(pa[i].y), f2t(pa[i].z), f2t(pa[i].w));
            *(uint4*)&AsBuf[r * AP + af4 * 4] = u;
        }
#pragma unroll
        for (int i = 0; i < 8; ++i) {
            int r = brow + i * 4;
            uint4 u = make_uint4(f2t(pb[i].x), f2t(pb[i].y), f2t(pb[i].z), f2t(pb[i].w));
            *(uint4*)&BsBuf[r * BP2 + bf4 * 4] = u;
        }
        if (32 < K) {
#pragma unroll
            for (int i = 0; i < 4; ++i)
                pa[i] = *(const float4*)&A[(size_t)(mbase + arow + i * 32) * K + 32 + af4 * 4];
#pragma unroll
            for (int i = 0; i < 8; ++i)
                pb[i] = *(const float4*)&B[(size_t)(32 + brow + i * 4) * N + nbase_local + bf4 * 4];
        }
        __syncthreads();

        int buf = 0;
        for (int kb = 0; kb < K; kb += 32) {
            unsigned* Asb = AsBuf + buf * ASZ;
            unsigned* Bsb = BsBuf + buf * BSZ2;

            // store prefetched block kb+32 into the other buffer
            if (kb + 32 < K) {
                unsigned* Asn = AsBuf + (buf ^ 1) * ASZ;
                unsigned* Bsn = BsBuf + (buf ^ 1) * BSZ2;
#pragma unroll
                for (int i = 0; i < 4; ++i) {
                    int r = arow + i * 32;
                    uint4 u = make_uint4(f2t(pa[i].x), f2t(pa[i].y), f2t(pa[i].z), f2t(pa[i].w));
                    *(uint4*)&Asn[r * AP + af4 * 4] = u;
                }
#pragma unroll
                for (int i = 0; i < 8; ++i) {
                    int r = brow + i * 4;
                    uint4 u = make_uint4(f2t(pb[i].x), f2t(pb[i].y), f2t(pb[i].z), f2t(pb[i].w));
                    *(uint4*)&Bsn[r * BP2 + bf4 * 4] = u;
                }
            }
            // prefetch block kb+64 into registers
            if (kb + 64 < K) {
#pragma unroll
                for (int i = 0; i < 4; ++i)
                    pa[i] = *(const float4*)&A[(size_t)(mbase + arow + i * 32) * K + kb + 64 + af4 * 4];
#pragma unroll
                for (int i = 0; i < 8; ++i)
                    pb[i] = *(const float4*)&B[(size_t)(kb + 64 + brow + i * 4) * N + nbase_local + bf4 * 4];
            }

            // compute on current buffer
#pragma unroll
            for (int ks = 0; ks < 4; ++ks) {
                const int k0 = ks * 8;
                unsigned a[4][4];
#pragma unroll
                for (int mt = 0; mt < 4; ++mt) {
                    int m = m0w + mt * 16;
                    a[mt][0] = Asb[(m + qr) * AP + k0 + qc];
                    a[mt][1] = Asb[(m + 8 + qr) * AP + k0 + qc];
                    a[mt][2] = Asb[(m + qr) * AP + k0 + 4 + qc];
                    a[mt][3] = Asb[(m + 8 + qr) * AP + k0 + 4 + qc];
                }
#pragma unroll
                for (int nt = 0; nt < 8; ++nt) {
                    int n = n0w + nt * 8;
                    unsigned b0 = Bsb[(k0 + qc) * BP2 + n + qr];
                    unsigned b1 = Bsb[(k0 + 4 + qc) * BP2 + n + qr];
#pragma unroll
                    for (int mt = 0; mt < 4; ++mt)
                        mma_tf32(acc[mt][nt], a[mt][0], a[mt][1], a[mt][2], a[mt][3], b0, b1);
                }
            }
            __syncthreads();
            buf ^= 1;
        }

        // epilogue (optional fused RoPE; cols in rotation pairs (2c, 2c+1))
#pragma unroll
        for (int mt = 0; mt < 4; ++mt) {
#pragma unroll
            for (int nt = 0; nt < 8; ++nt) {
                int row = mbase + m0w + mt * 16 + qr;
                int lcol = nbase_local + n0w + nt * 8 + 2 * qc;
                float2 v0 = make_float2(acc[mt][nt][0], acc[mt][nt][1]);
                float2 v1 = make_float2(acc[mt][nt][2], acc[mt][nt][3]);
                if (ROPE_EPI) {
                    int d = lcol & 63;
                    float2 f0 = *(const float2*)&F[(size_t)row * 64 + d];
                    float2 f1 = *(const float2*)&F[(size_t)(row + 8) * 64 + d];
                    v0 = make_float2(v0.x * f0.x - v0.y * f0.y, v0.x * f0.y + v0.y * f0.x);
                    v1 = make_float2(v1.x * f1.x - v1.y * f1.y, v1.x * f1.y + v1.y * f1.x);
                }
                *(float2*)&C[(size_t)row * N + lcol] = v0;
                *(float2*)&C[(size_t)(row + 8) * N + lcol] = v1;
            }
        }
    }
};

// ---- fused QKV + RoPE (V does NOT get RoPE); n-tile = 256 ------------------
__global__ __launch_bounds__(256)
void qkv_gemm_kernel(const float* __restrict__ A,
                     const float* __restrict__ Wq,
                     const float* __restrict__ Wk,
                     const float* __restrict__ Wv,
                     const float* __restrict__ F,
                     float* __restrict__ Qp,
                     float* __restrict__ Kp,
                     float* __restrict__ Vp) {
    const int mbase = blockIdx.y * 128;
    const int nbase = blockIdx.x * 256;
    if (nbase < QSTRIDE) {
        GemmCore::run<true>(A, Wq, Qp, F, QSTRIDE, E, mbase, nbase);
    } else if (nbase < QSTRIDE + KSTRIDE) {
        GemmCore::run<true>(A, Wk, Kp, F, KSTRIDE, E, mbase, nbase - QSTRIDE);
    } else {
        GemmCore::run<false>(A, Wv, Vp, nullptr, KSTRIDE, E, mbase,
                             nbase - QSTRIDE - KSTRIDE);
    }
}

// ---- plain GEMM (output projection) ----------------------------------------
__global__ __launch_bounds__(256)
void tgemm_kernel(const float* __restrict__ A,
                  const float* __restrict__ B,
                  float* __restrict__ C,
                  int M, int N, int K) {
    GemmCore::run<false>(A, B, C, nullptr, N, K, blockIdx.y * 128, blockIdx.x * 256);
}

// ============================================================================
// TF32 flash attention (exact R5 design — best known): 128 q-rows/CTA,
// 4 warps x 32 rows (mt=2, nt=8), V row-major, conflict-free pitches.
// ============================================================================
#define FPQ 68
#define FPV 72
#define FA_SMEM_WORDS (128*FPQ + 64*FPQ + 64*FPV + 128*FPQ)
#define FA_SMEM_BYTES (FA_SMEM_WORDS * 4)   // 105472

__global__ __launch_bounds__(128)
void flash_tc_kernel(const float* __restrict__ Q,
                     const float* __restrict__ Kg,
                     const float* __restrict__ Vg,
                     float* __restrict__ O) {
    const int h = blockIdx.y;
    const int qt = (gridDim.x - 1) - blockIdx.x;
    const int qbase = qt * 128;
    const int kh = h >> 2;

    extern __shared__ unsigned smu[];
    unsigned* Qs = smu;
    unsigned* Ks = Qs + 128 * FPQ;
    unsigned* Vs = Ks + 64 * FPQ;
    unsigned* Ps = Vs + 64 * FPV;

    const int tid = threadIdx.x;
    const int lane = tid & 31;
    const int warp = tid >> 5;
    const int m0 = warp * 32;
    const int qr = lane >> 2;
    const int qc = lane & 3;
    const int f4 = tid & 15;
    const int row0 = tid >> 4;

#pragma unroll
    for (int i = 0; i < 16; ++i) {
        int r = row0 + i * 8;
        float4 v = *(const float4*)&Q[(size_t)(qbase + r) * QSTRIDE + h * D + f4 * 4];
        uint4 u = make_uint4(f2t(v.x), f2t(v.y), f2t(v.z), f2t(v.w));
        *(uint4*)&Qs[r * FPQ + f4 * 4] = u;
    }

    float o[2][8][4];
#pragma unroll
    for (int mt = 0; mt < 2; ++mt)
#pragma unroll
        for (int nt = 0; nt < 8; ++nt)
#pragma unroll
            for (int j = 0; j < 4; ++j) o[mt][nt][j] = 0.f;
    float mr[2][2], lr[2][2];
#pragma unroll
    for (int mt = 0; mt < 2; ++mt) {
        mr[mt][0] = -1e30f; mr[mt][1] = -1e30f;
        lr[mt][0] = 0.f;    lr[mt][1] = 0.f;
    }

    const int kt_max = 2 * qt + 1;
    for (int kt = 0; kt <= kt_max; ++kt) {
        __syncthreads();
        const int kbase = kt * 64;

#pragma unroll
        for (int i = 0; i < 8; ++i) {
            int r = row0 + i * 8;
            float4 v = *(const float4*)&Kg[(size_t)(kbase + r) * KSTRIDE + kh * D + f4 * 4];
            uint4 u = make_uint4(f2t(v.x), f2t(v.y), f2t(v.z), f2t(v.w));
            *(uint4*)&Ks[r * FPQ + f4 * 4] = u;
        }
#pragma unroll
        for (int i = 0; i < 8; ++i) {
            int r = row0 + i * 8;
            float4 v = *(const float4*)&Vg[(size_t)(kbase + r) * KSTRIDE + kh * D + f4 * 4];
            uint4 u = make_uint4(f2t(v.x), f2t(v.y), f2t(v.z), f2t(v.w));
            *(uint4*)&Vs[r * FPV + f4 * 4] = u;
        }
        __syncthreads();

        if (kbase > qbase + m0 + 31) continue;

        float s[2][8][4];
#pragma unroll
        for (int mt = 0; mt < 2; ++mt)
#pragma unroll
            for (int nt = 0; nt < 8; ++nt)
#pragma unroll
                for (int j = 0; j < 4; ++j) s[mt][nt][j] = 0.f;

#pragma unroll
        for (int ks = 0; ks < 8; ++ks) {
            const int k0 = ks * 8;
            unsigned a[2][4];
#pragma unroll
            for (int mt = 0; mt < 2; ++mt) {
                int m = m0 + mt * 16;
                a[mt][0] = Qs[(m + qr) * FPQ + k0 + qc];
                a[mt][1] = Qs[(m + 8 + qr) * FPQ + k0 + qc];
                a[mt][2] = Qs[(m + qr) * FPQ + k0 + 4 + qc];
                a[mt][3] = Qs[(m + 8 + qr) * FPQ + k0 + 4 + qc];
            }
#pragma unroll
            for (int nt = 0; nt < 8; ++nt) {
                unsigned b0 = Ks[(nt * 8 + qr) * FPQ + k0 + qc];
                unsigned b1 = Ks[(nt * 8 + qr) * FPQ + k0 + 4 + qc];
#pragma unroll
                for (int mt = 0; mt < 2; ++mt)
                    mma_tf32(s[mt][nt], a[mt][0], a[mt][1], a[mt][2], a[mt][3], b0, b1);
            }
        }

#pragma unroll
        for (int mt = 0; mt < 2; ++mt) {
            const int q_lo = qbase + m0 + mt * 16 + qr;
            const int q_hi = q_lo + 8;
            const bool need_mask = (kbase + 63 > q_lo);
#pragma unroll
            for (int nt = 0; nt < 8; ++nt) {
#pragma unroll
                for (int j = 0; j < 2; ++j) {
                    int kcol = kbase + nt * 8 + 2 * qc + j;
                    float v0 = s[mt][nt][j] * 0.125f;
                    float v1 = s[mt][nt][2 + j] * 0.125f;
                    if (need_mask && kcol > q_lo) v0 = -1e30f;
                    if (need_mask && kcol > q_hi) v1 = -1e30f;
                    s[mt][nt][j] = v0;
                    s[mt][nt][2 + j] = v1;
                }
            }

            float tm_lo = -1e30f, tm_hi = -1e30f;
#pragma unroll
            for (int nt = 0; nt < 8; ++nt) {
                tm_lo = fmaxf(tm_lo, fmaxf(s[mt][nt][0], s[mt][nt][1]));
                tm_hi = fmaxf(tm_hi, fmaxf(s[mt][nt][2], s[mt][nt][3]));
            }
#pragma unroll
            for (int off = 1; off <= 2; off <<= 1) {
                tm_lo = fmaxf(tm_lo, __shfl_xor_sync(0xffffffffu, tm_lo, off));
                tm_hi = fmaxf(tm_hi, __shfl_xor_sync(0xffffffffu, tm_hi, off));
            }
            float mn_lo = fmaxf(mr[mt][0], tm_lo);
            float mn_hi = fmaxf(mr[mt][1], tm_hi);
            float fac_lo = __expf(mr[mt][0] - mn_lo);
            float fac_hi = __expf(mr[mt][1] - mn_hi);

            float sum_lo = 0.f, sum_hi = 0.f;
#pragma unroll
            for (int nt = 0; nt < 8; ++nt) {
                float p0 = __expf(s[mt][nt][0] - mn_lo);
                float p1 = __expf(s[mt][nt][1] - mn_lo);
                float p2 = __expf(s[mt][nt][2] - mn_hi);
                float p3 = __expf(s[mt][nt][3] - mn_hi);
                s[mt][nt][0] = p0; s[mt][nt][1] = p1;
                s[mt][nt][2] = p2; s[mt][nt][3] = p3;
                sum_lo += p0 + p1;
                sum_hi += p2 + p3;
            }
#pragma unroll
            for (int off = 1; off <= 2; off <<= 1) {
                sum_lo += __shfl_xor_sync(0xffffffffu, sum_lo, off);
                sum_hi += __shfl_xor_sync(0xffffffffu, sum_hi, off);
            }
            lr[mt][0] = lr[mt][0] * fac_lo + sum_lo;
            lr[mt][1] = lr[mt][1] * fac_hi + sum_hi;
            mr[mt][0] = mn_lo;
            mr[mt][1] = mn_hi;

#pragma unroll
            for (int nt = 0; nt < 8; ++nt) {
                o[mt][nt][0] *= fac_lo; o[mt][nt][1] *= fac_lo;
                o[mt][nt][2] *= fac_hi; o[mt][nt][3] *= fac_hi;
            }

#pragma unroll
            for (int nt = 0; nt < 8; ++nt) {
                int r = m0 + mt * 16 + qr;
                int c = nt * 8 + 2 * qc;
                Ps[r * FPQ + c]           = f2t(s[mt][nt][0]);
                Ps[r * FPQ + c + 1]       = f2t(s[mt][nt][1]);
                Ps[(r + 8) * FPQ + c]     = f2t(s[mt][nt][2]);
                Ps[(r + 8) * FPQ + c + 1] = f2t(s[mt][nt][3]);
            }
        }
        __syncwarp();

#pragma unroll
        for (int ks = 0; ks < 8; ++ks) {
            const int k0 = ks * 8;
            unsigned a[2][4];
#pragma unroll
            for (int mt = 0; mt < 2; ++mt) {
                int m = m0 + mt * 16;
                a[mt][0] = Ps[(m + qr) * FPQ + k0 + qc];
                a[mt][1] = Ps[(m + 8 + qr) * FPQ + k0 + qc];
                a[mt][2] = Ps[(m + qr) * FPQ + k0 + 4 + qc];
                a[mt][3] = Ps[(m + 8 + qr) * FPQ + k0 + 4 + qc];
            }
#pragma unroll
            for (int nt = 0; nt < 8; ++nt) {
                unsigned b0 = Vs[(k0 + qc) * FPV + nt * 8 + qr];
                unsigned b1 = Vs[(k0 + 4 + qc) * FPV + nt * 8 + qr];
#pragma unroll
                for (int mt = 0; mt < 2; ++mt)
                    mma_tf32(o[mt][nt], a[mt][0], a[mt][1], a[mt][2], a[mt][3], b0, b1);
            }
        }
    }

#pragma unroll
    for (int mt = 0; mt < 2; ++mt) {
        float inv_lo = 1.f / lr[mt][0];
        float inv_hi = 1.f / lr[mt][1];
#pragma unroll
        for (int nt = 0; nt < 8; ++nt) {
            int row = qbase + m0 + mt * 16 + qr;
            int col = h * D + nt * 8 + 2 * qc;
            *(float2*)&O[(size_t)row * QSTRIDE + col] =
                make_float2(o[mt][nt][0] * inv_lo, o[mt][nt][1] * inv_lo);
            *(float2*)&O[(size_t)(row + 8) * QSTRIDE + col] =
                make_float2(o[mt][nt][2] * inv_hi, o[mt][nt][3] * inv_hi);
        }
    }
}

// ---------------- launch ---------------------------------------------------
extern "C" void kernel_launch(void* const* d_in, const int* in_sizes, int n_in,
                              void* d_out, int out_size) {
    const float* x  = (const float*)d_in[0];
    const float* fc = (const float*)d_in[1];
    const float* Wq = (const float*)d_in[3];
    const float* Wk = (const float*)d_in[4];
    const float* Wv = (const float*)d_in[5];
    const float* Wo = (const float*)d_in[6];
    float* out = (float*)d_out;

    float *Q, *K, *V, *A;
    cudaGetSymbolAddress((void**)&Q, g_Q);
    cudaGetSymbolAddress((void**)&K, g_K);
    cudaGetSymbolAddress((void**)&V, g_V);
    cudaGetSymbolAddress((void**)&A, g_A);

    cudaFuncSetAttribute(qkv_gemm_kernel,
                         cudaFuncAttributeMaxDynamicSharedMemorySize, GEMM_SMEM_BYTES);
    cudaFuncSetAttribute(tgemm_kernel,
                         cudaFuncAttributeMaxDynamicSharedMemorySize, GEMM_SMEM_BYTES);
    cudaFuncSetAttribute(flash_tc_kernel,
                         cudaFuncAttributeMaxDynamicSharedMemorySize, FA_SMEM_BYTES);

    // fused QKV projection + RoPE (Q,K only), 128x256 tiles
    qkv_gemm_kernel<<<dim3(NTOT / 256, S / 128), 256, GEMM_SMEM_BYTES>>>(
        x, Wq, Wk, Wv, fc, Q, K, V);

    // causal GQA flash attention
    flash_tc_kernel<<<dim3(S / 128, HQ), 128, FA_SMEM_BYTES>>>(Q, K, V, A);

    // output projection, 128x256 tiles
    tgemm_kernel<<<dim3(E / 256, S / 128), 256, GEMM_SMEM_BYTES>>>(A, Wo, out, S, E, E);
}

// round 13
// speedup vs baseline: 1.2006x; 1.0848x over previous
#include <cuda_runtime.h>
#include <cuda_bf16.h>
#include <cstdint>

// Problem constants
#define S      2048
#define E      2048
#define HQ     32
#define HKV    8
#define D      64
#define QSTRIDE (HQ*D)    // 2048
#define KSTRIDE (HKV*D)   // 512
#define NTOT   (QSTRIDE + 2*KSTRIDE)  // 3072

// ---------------- scratch (device globals; no allocation allowed) ----------
__device__ float g_Q[S * QSTRIDE];
__device__ float g_K[S * KSTRIDE];
__device__ float g_V[S * KSTRIDE];
__device__ float g_A[S * QSTRIDE];

// ---------------- helpers ---------------------------------------------------
__device__ __forceinline__ unsigned f2t(float f) {
    unsigned u;
    asm("cvt.rna.tf32.f32 %0, %1;" : "=r"(u) : "f"(f));
    return u;
}

__device__ __forceinline__ void mma_tf32(float c[4],
                                         unsigned a0, unsigned a1, unsigned a2, unsigned a3,
                                         unsigned b0, unsigned b1) {
    asm volatile(
        "mma.sync.aligned.m16n8k8.row.col.f32.tf32.tf32.f32 "
        "{%0,%1,%2,%3}, {%4,%5,%6,%7}, {%8,%9}, {%0,%1,%2,%3};\n"
        : "+f"(c[0]), "+f"(c[1]), "+f"(c[2]), "+f"(c[3])
        : "r"(a0), "r"(a1), "r"(a2), "r"(a3), "r"(b0), "r"(b1));
}

// GEMM smem geometry: A row-major [128][36], B [32][136], double buffered.
#define AP   36
#define BP   136
#define ASZ  (128 * AP)
#define BSZ  (32 * BP)
#define GEMM_SMEM_BYTES ((2 * ASZ + 2 * BSZ) * 4)   // 71680

// ============================================================================
// GEMM core (exact R5 design — local optimum, do not touch).
// ============================================================================
struct GemmCore {
    template <bool ROPE_EPI>
    static __device__ __forceinline__ void run(
        const float* __restrict__ A, const float* __restrict__ B,
        float* __restrict__ C, const float* __restrict__ F,
        int N, int K, int mbase, int nbase_local) {

        extern __shared__ unsigned smg[];
        unsigned* AsBuf = smg;
        unsigned* BsBuf = smg + 2 * ASZ;

        const int tid  = threadIdx.x;
        const int lane = tid & 31;
        const int warp = tid >> 5;
        const int m0w = (warp >> 1) * 64;
        const int n0w = (warp & 1) * 64;
        const int qr = lane >> 2, qc = lane & 3;

        float acc[4][8][4];
#pragma unroll
        for (int mt = 0; mt < 4; ++mt)
#pragma unroll
            for (int nt = 0; nt < 8; ++nt)
#pragma unroll
                for (int j = 0; j < 4; ++j) acc[mt][nt][j] = 0.f;

        const int arow = tid >> 3, af4 = tid & 7;
        const int brow = tid >> 5, bf4 = tid & 31;

        float4 pa[8], pb[8];

#pragma unroll
        for (int i = 0; i < 8; ++i)
            pa[i] = *(const float4*)&A[(size_t)(mbase + arow + i * 16) * K + af4 * 4];
#pragma unroll
        for (int i = 0; i < 8; ++i)
            pb[i] = *(const float4*)&B[(size_t)(brow + i * 4) * N + nbase_local + bf4 * 4];
#pragma unroll
        for (int i = 0; i < 8; ++i) {
            int r = arow + i * 16;
            uint4 u = make_uint4(f2t(pa[i].x), f2t(pa[i].y), f2t(pa[i].z), f2t(pa[i].w));
            *(uint4*)&AsBuf[r * AP + af4 * 4] = u;
        }
#pragma unroll
        for (int i = 0; i < 8; ++i) {
            int r = brow + i * 4;
            uint4 u = make_uint4(f2t(pb[i].x), f2t(pb[i].y), f2t(pb[i].z), f2t(pb[i].w));
            *(uint4*)&BsBuf[r * BP + bf4 * 4] = u;
        }
        if (32 < K) {
#pragma unroll
            for (int i = 0; i < 8; ++i)
                pa[i] = *(const float4*)&A[(size_t)(mbase + arow + i * 16) * K + 32 + af4 * 4];
#pragma unroll
            for (int i = 0; i < 8; ++i)
                pb[i] = *(const float4*)&B[(size_t)(32 + brow + i * 4) * N + nbase_local + bf4 * 4];
        }
        __syncthreads();

        int buf = 0;
        for (int kb = 0; kb < K; kb += 32) {
            unsigned* Asb = AsBuf + buf * ASZ;
            unsigned* Bsb = BsBuf + buf * BSZ;

            if (kb + 32 < K) {
                unsigned* Asn = AsBuf + (buf ^ 1) * ASZ;
                unsigned* Bsn = BsBuf + (buf ^ 1) * BSZ;
#pragma unroll
                for (int i = 0; i < 8; ++i) {
                    int r = arow + i * 16;
                    uint4 u = make_uint4(f2t(pa[i].x), f2t(pa[i].y), f2t(pa[i].z), f2t(pa[i].w));
                    *(uint4*)&Asn[r * AP + af4 * 4] = u;
                }
#pragma unroll
                for (int i = 0; i < 8; ++i) {
                    int r = brow + i * 4;
                    uint4 u = make_uint4(f2t(pb[i].x), f2t(pb[i].y), f2t(pb[i].z), f2t(pb[i].w));
                    *(uint4*)&Bsn[r * BP + bf4 * 4] = u;
                }
            }
            if (kb + 64 < K) {
#pragma unroll
                for (int i = 0; i < 8; ++i)
                    pa[i] = *(const float4*)&A[(size_t)(mbase + arow + i * 16) * K + kb + 64 + af4 * 4];
#pragma unroll
                for (int i = 0; i < 8; ++i)
                    pb[i] = *(const float4*)&B[(size_t)(kb + 64 + brow + i * 4) * N + nbase_local + bf4 * 4];
            }

#pragma unroll
            for (int ks = 0; ks < 4; ++ks) {
                const int k0 = ks * 8;
                unsigned a[4][4];
#pragma unroll
                for (int mt = 0; mt < 4; ++mt) {
                    int m = m0w + mt * 16;
                    a[mt][0] = Asb[(m + qr) * AP + k0 + qc];
                    a[mt][1] = Asb[(m + 8 + qr) * AP + k0 + qc];
                    a[mt][2] = Asb[(m + qr) * AP + k0 + 4 + qc];
                    a[mt][3] = Asb[(m + 8 + qr) * AP + k0 + 4 + qc];
                }
#pragma unroll
                for (int nt = 0; nt < 8; ++nt) {
                    int n = n0w + nt * 8;
                    unsigned b0 = Bsb[(k0 + qc) * BP + n + qr];
                    unsigned b1 = Bsb[(k0 + 4 + qc) * BP + n + qr];
#pragma unroll
                    for (int mt = 0; mt < 4; ++mt)
                        mma_tf32(acc[mt][nt], a[mt][0], a[mt][1], a[mt][2], a[mt][3], b0, b1);
                }
            }
            __syncthreads();
            buf ^= 1;
        }

#pragma unroll
        for (int mt = 0; mt < 4; ++mt) {
#pragma unroll
            for (int nt = 0; nt < 8; ++nt) {
                int row = mbase + m0w + mt * 16 + qr;
                int lcol = nbase_local + n0w + nt * 8 + 2 * qc;
                float2 v0 = make_float2(acc[mt][nt][0], acc[mt][nt][1]);
                float2 v1 = make_float2(acc[mt][nt][2], acc[mt][nt][3]);
                if (ROPE_EPI) {
                    int d = lcol & 63;
                    float2 f0 = *(const float2*)&F[(size_t)row * 64 + d];
                    float2 f1 = *(const float2*)&F[(size_t)(row + 8) * 64 + d];
                    v0 = make_float2(v0.x * f0.x - v0.y * f0.y, v0.x * f0.y + v0.y * f0.x);
                    v1 = make_float2(v1.x * f1.x - v1.y * f1.y, v1.x * f1.y + v1.y * f1.x);
                }
                *(float2*)&C[(size_t)row * N + lcol] = v0;
                *(float2*)&C[(size_t)(row + 8) * N + lcol] = v1;
            }
        }
    }
};

__global__ __launch_bounds__(128)
void qkv_gemm_kernel(const float* __restrict__ A,
                     const float* __restrict__ Wq,
                     const float* __restrict__ Wk,
                     const float* __restrict__ Wv,
                     const float* __restrict__ F,
                     float* __restrict__ Qp,
                     float* __restrict__ Kp,
                     float* __restrict__ Vp) {
    const int mbase = blockIdx.y * 128;
    const int nbase = blockIdx.x * 128;
    if (nbase < QSTRIDE) {
        GemmCore::run<true>(A, Wq, Qp, F, QSTRIDE, E, mbase, nbase);
    } else if (nbase < QSTRIDE + KSTRIDE) {
        GemmCore::run<true>(A, Wk, Kp, F, KSTRIDE, E, mbase, nbase - QSTRIDE);
    } else {
        GemmCore::run<false>(A, Wv, Vp, nullptr, KSTRIDE, E, mbase,
                             nbase - QSTRIDE - KSTRIDE);
    }
}

__global__ __launch_bounds__(128)
void tgemm_kernel(const float* __restrict__ A,
                  const float* __restrict__ B,
                  float* __restrict__ C,
                  int M, int N, int K) {
    GemmCore::run<false>(A, B, C, nullptr, N, K, blockIdx.y * 128, blockIdx.x * 128);
}

// ============================================================================
// GQA-shared TF32 flash attention: CTA = 64 seq rows x 4 q-heads of one
// kv-head (256 q-rows share one K/V tile). 256 threads, 8 warps, all
// consumers: warp w -> head 4*kh + (w>>1), seq rows (w&1)*32 + [0,32).
// K/V loaded ONCE per CTA per tile (4x traffic reduction), zero inactive
// warp iterations (kt = 0..qt exactly).
// ============================================================================
#define FPQ 68
#define FPV 72
#define FA_SMEM_WORDS (256*FPQ + 64*FPQ + 64*FPV + 256*FPQ)
#define FA_SMEM_BYTES (FA_SMEM_WORDS * 4)   // 175616

__global__ __launch_bounds__(256)
void flash_gqa_kernel(const float* __restrict__ Q,
                      const float* __restrict__ Kg,
                      const float* __restrict__ Vg,
                      float* __restrict__ O) {
    const int kh = blockIdx.y;                       // kv head 0..7
    const int qt = (gridDim.x - 1) - blockIdx.x;     // heavy tiles first
    const int qbase = qt * 64;

    extern __shared__ unsigned smu[];
    unsigned* Qs = smu;                  // [256][FPQ]  row = h_local*64 + seq
    unsigned* Ks = Qs + 256 * FPQ;       // [64][FPQ]
    unsigned* Vs = Ks + 64 * FPQ;        // [64][FPV]   row-major [k][d]
    unsigned* Ps = Vs + 64 * FPV;        // [256][FPQ]

    const int tid = threadIdx.x;
    const int lane = tid & 31;
    const int warp = tid >> 5;
    const int h_local = warp >> 1;                   // 0..3
    const int h = kh * 4 + h_local;                  // global q head
    const int m0q = (warp & 1) * 32;                 // seq offset within tile
    const int prow = h_local * 64 + m0q;             // base row in Qs/Ps
    const int qr = lane >> 2;
    const int qc = lane & 3;
    const int f4 = tid & 15;
    const int row0 = tid >> 4;                       // 0..15

    // ---- load Q: 256 rows (4 heads x 64 seq) x 16 f4 ----
#pragma unroll
    for (int i = 0; i < 16; ++i) {
        int r = row0 + i * 16;                       // smem row 0..255
        int hl = r >> 6;                             // head_local
        int sr = r & 63;                             // seq row
        float4 v = *(const float4*)&Q[(size_t)(qbase + sr) * QSTRIDE
                                      + (kh * 4 + hl) * D + f4 * 4];
        uint4 u = make_uint4(f2t(v.x), f2t(v.y), f2t(v.z), f2t(v.w));
        *(uint4*)&Qs[r * FPQ + f4 * 4] = u;
    }

    float o[2][8][4];
#pragma unroll
    for (int mt = 0; mt < 2; ++mt)
#pragma unroll
        for (int nt = 0; nt < 8; ++nt)
#pragma unroll
            for (int j = 0; j < 4; ++j) o[mt][nt][j] = 0.f;
    float mr[2][2], lr[2][2];
#pragma unroll
    for (int mt = 0; mt < 2; ++mt) {
        mr[mt][0] = -1e30f; mr[mt][1] = -1e30f;
        lr[mt][0] = 0.f;    lr[mt][1] = 0.f;
    }

    for (int kt = 0; kt <= qt; ++kt) {
        __syncthreads();                 // prior reads of Ks/Vs complete
        const int kbase = kt * 64;

        // ---- load K/V tile: 256 threads, 4 f4 each per tensor ----
#pragma unroll
        for (int i = 0; i < 4; ++i) {
            int r = row0 + i * 16;
            float4 v = *(const float4*)&Kg[(size_t)(kbase + r) * KSTRIDE + kh * D + f4 * 4];
            uint4 u = make_uint4(f2t(v.x), f2t(v.y), f2t(v.z), f2t(v.w));
            *(uint4*)&Ks[r * FPQ + f4 * 4] = u;
        }
#pragma unroll
        for (int i = 0; i < 4; ++i) {
            int r = row0 + i * 16;
            float4 v = *(const float4*)&Vg[(size_t)(kbase + r) * KSTRIDE + kh * D + f4 * 4];
            uint4 u = make_uint4(f2t(v.x), f2t(v.y), f2t(v.z), f2t(v.w));
            *(uint4*)&Vs[r * FPV + f4 * 4] = u;
        }
        __syncthreads();

        // ---- S = Q K^T ----
        float s[2][8][4];
#pragma unroll
        for (int mt = 0; mt < 2; ++mt)
#pragma unroll
            for (int nt = 0; nt < 8; ++nt)
#pragma unroll
                for (int j = 0; j < 4; ++j) s[mt][nt][j] = 0.f;

#pragma unroll
        for (int ks = 0; ks < 8; ++ks) {
            const int k0 = ks * 8;
            unsigned a[2][4];
#pragma unroll
            for (int mt = 0; mt < 2; ++mt) {
                int m = prow + mt * 16;
                a[mt][0] = Qs[(m + qr) * FPQ + k0 + qc];
                a[mt][1] = Qs[(m + 8 + qr) * FPQ + k0 + qc];
                a[mt][2] = Qs[(m + qr) * FPQ + k0 + 4 + qc];
                a[mt][3] = Qs[(m + 8 + qr) * FPQ + k0 + 4 + qc];
            }
#pragma unroll
            for (int nt = 0; nt < 8; ++nt) {
                unsigned b0 = Ks[(nt * 8 + qr) * FPQ + k0 + qc];
                unsigned b1 = Ks[(nt * 8 + qr) * FPQ + k0 + 4 + qc];
#pragma unroll
                for (int mt = 0; mt < 2; ++mt)
                    mma_tf32(s[mt][nt], a[mt][0], a[mt][1], a[mt][2], a[mt][3], b0, b1);
            }
        }

        // ---- scale + causal mask + online softmax (per mt) ----
        const bool diag = (kt == qt);
#pragma unroll
        for (int mt = 0; mt < 2; ++mt) {
            const int q_lo = qbase + m0q + mt * 16 + qr;
            const int q_hi = q_lo + 8;
#pragma unroll
            for (int nt = 0; nt < 8; ++nt) {
#pragma unroll
                for (int j = 0; j < 2; ++j) {
                    int kcol = kbase + nt * 8 + 2 * qc + j;
                    float v0 = s[mt][nt][j] * 0.125f;
                    float v1 = s[mt][nt][2 + j] * 0.125f;
                    if (diag && kcol > q_lo) v0 = -1e30f;
                    if (diag && kcol > q_hi) v1 = -1e30f;
                    s[mt][nt][j] = v0;
                    s[mt][nt][2 + j] = v1;
                }
            }

            float tm_lo = -1e30f, tm_hi = -1e30f;
#pragma unroll
            for (int nt = 0; nt < 8; ++nt) {
                tm_lo = fmaxf(tm_lo, fmaxf(s[mt][nt][0], s[mt][nt][1]));
                tm_hi = fmaxf(tm_hi, fmaxf(s[mt][nt][2], s[mt][nt][3]));
            }
#pragma unroll
            for (int off = 1; off <= 2; off <<= 1) {
                tm_lo = fmaxf(tm_lo, __shfl_xor_sync(0xffffffffu, tm_lo, off));
                tm_hi = fmaxf(tm_hi, __shfl_xor_sync(0xffffffffu, tm_hi, off));
            }
            float mn_lo = fmaxf(mr[mt][0], tm_lo);
            float mn_hi = fmaxf(mr[mt][1], tm_hi);
            float fac_lo = __expf(mr[mt][0] - mn_lo);
            float fac_hi = __expf(mr[mt][1] - mn_hi);

            float sum_lo = 0.f, sum_hi = 0.f;
#pragma unroll
            for (int nt = 0; nt < 8; ++nt) {
                float p0 = __expf(s[mt][nt][0] - mn_lo);
                float p1 = __expf(s[mt][nt][1] - mn_lo);
                float p2 = __expf(s[mt][nt][2] - mn_hi);
                float p3 = __expf(s[mt][nt][3] - mn_hi);
                s[mt][nt][0] = p0; s[mt][nt][1] = p1;
                s[mt][nt][2] = p2; s[mt][nt][3] = p3;
                sum_lo += p0 + p1;
                sum_hi += p2 + p3;
            }
#pragma unroll
            for (int off = 1; off <= 2; off <<= 1) {
                sum_lo += __shfl_xor_sync(0xffffffffu, sum_lo, off);
                sum_hi += __shfl_xor_sync(0xffffffffu, sum_hi, off);
            }
            lr[mt][0] = lr[mt][0] * fac_lo + sum_lo;
            lr[mt][1] = lr[mt][1] * fac_hi + sum_hi;
            mr[mt][0] = mn_lo;
            mr[mt][1] = mn_hi;

#pragma unroll
            for (int nt = 0; nt < 8; ++nt) {
                o[mt][nt][0] *= fac_lo; o[mt][nt][1] *= fac_lo;
                o[mt][nt][2] *= fac_hi; o[mt][nt][3] *= fac_hi;
            }

            // write P fragments to smem (warp-private rows)
#pragma unroll
            for (int nt = 0; nt < 8; ++nt) {
                int r = prow + mt * 16 + qr;
                int c = nt * 8 + 2 * qc;
                Ps[r * FPQ + c]           = f2t(s[mt][nt][0]);
                Ps[r * FPQ + c + 1]       = f2t(s[mt][nt][1]);
                Ps[(r + 8) * FPQ + c]     = f2t(s[mt][nt][2]);
                Ps[(r + 8) * FPQ + c + 1] = f2t(s[mt][nt][3]);
            }
        }
        __syncwarp();

        // ---- O += P V ----
#pragma unroll
        for (int ks = 0; ks < 8; ++ks) {
            const int k0 = ks * 8;
            unsigned a[2][4];
#pragma unroll
            for (int mt = 0; mt < 2; ++mt) {
                int m = prow + mt * 16;
                a[mt][0] = Ps[(m + qr) * FPQ + k0 + qc];
                a[mt][1] = Ps[(m + 8 + qr) * FPQ + k0 + qc];
                a[mt][2] = Ps[(m + qr) * FPQ + k0 + 4 + qc];
                a[mt][3] = Ps[(m + 8 + qr) * FPQ + k0 + 4 + qc];
            }
#pragma unroll
            for (int nt = 0; nt < 8; ++nt) {
                unsigned b0 = Vs[(k0 + qc) * FPV + nt * 8 + qr];
                unsigned b1 = Vs[(k0 + 4 + qc) * FPV + nt * 8 + qr];
#pragma unroll
                for (int mt = 0; mt < 2; ++mt)
                    mma_tf32(o[mt][nt], a[mt][0], a[mt][1], a[mt][2], a[mt][3], b0, b1);
            }
        }
    }

    // ---- normalize + write out ----
#pragma unroll
    for (int mt = 0; mt < 2; ++mt) {
        float inv_lo = 1.f / lr[mt][0];
        float inv_hi = 1.f / lr[mt][1];
#pragma unroll
        for (int nt = 0; nt < 8; ++nt) {
            int row = qbase + m0q + mt * 16 + qr;
            int col = h * D + nt * 8 + 2 * qc;
            *(float2*)&O[(size_t)row * QSTRIDE + col] =
                make_float2(o[mt][nt][0] * inv_lo, o[mt][nt][1] * inv_lo);
            *(float2*)&O[(size_t)(row + 8) * QSTRIDE + col] =
                make_float2(o[mt][nt][2] * inv_hi, o[mt][nt][3] * inv_hi);
        }
    }
}

// ---------------- launch ---------------------------------------------------
extern "C" void kernel_launch(void* const* d_in, const int* in_sizes, int n_in,
                              void* d_out, int out_size) {
    const float* x  = (const float*)d_in[0];
    const float* fc = (const float*)d_in[1];
    const float* Wq = (const float*)d_in[3];
    const float* Wk = (const float*)d_in[4];
    const float* Wv = (const float*)d_in[5];
    const float* Wo = (const float*)d_in[6];
    float* out = (float*)d_out;

    float *Q, *K, *V, *A;
    cudaGetSymbolAddress((void**)&Q, g_Q);
    cudaGetSymbolAddress((void**)&K, g_K);
    cudaGetSymbolAddress((void**)&V, g_V);
    cudaGetSymbolAddress((void**)&A, g_A);

    cudaFuncSetAttribute(qkv_gemm_kernel,
                         cudaFuncAttributeMaxDynamicSharedMemorySize, GEMM_SMEM_BYTES);
    cudaFuncSetAttribute(tgemm_kernel,
                         cudaFuncAttributeMaxDynamicSharedMemorySize, GEMM_SMEM_BYTES);
    cudaFuncSetAttribute(flash_gqa_kernel,
                         cudaFuncAttributeMaxDynamicSharedMemorySize, FA_SMEM_BYTES);

    // fused QKV projection + RoPE (Q,K only)
    qkv_gemm_kernel<<<dim3(NTOT / 128, S / 128), 128, GEMM_SMEM_BYTES>>>(
        x, Wq, Wk, Wv, fc, Q, K, V);

    // GQA-shared causal flash attention: grid (q-tiles, kv-heads)
    flash_gqa_kernel<<<dim3(S / 64, HKV), 256, FA_SMEM_BYTES>>>(Q, K, V, A);

    // output projection
    tgemm_kernel<<<dim3(E / 128, S / 128), 128, GEMM_SMEM_BYTES>>>(A, Wo, out, S, E, E);
}

// round 14
// speedup vs baseline: 1.2032x; 1.0022x over previous
#include <cuda_runtime.h>
#include <cuda_bf16.h>
#include <cstdint>

// Problem constants
#define S      2048
#define E      2048
#define HQ     32
#define HKV    8
#define D      64
#define QSTRIDE (HQ*D)    // 2048
#define KSTRIDE (HKV*D)   // 512
#define NTOT   (QSTRIDE + 2*KSTRIDE)  // 3072

// ---------------- scratch (device globals; no allocation allowed) ----------
__device__ float g_Q[S * QSTRIDE];
__device__ float g_K[S * KSTRIDE];
__device__ float g_V[S * KSTRIDE];
__device__ float g_A[S * QSTRIDE];

// ---------------- helpers ---------------------------------------------------
__device__ __forceinline__ unsigned f2t(float f) {
    unsigned u;
    asm("cvt.rna.tf32.f32 %0, %1;" : "=r"(u) : "f"(f));
    return u;
}

__device__ __forceinline__ void mma_tf32(float c[4],
                                         unsigned a0, unsigned a1, unsigned a2, unsigned a3,
                                         unsigned b0, unsigned b1) {
    asm volatile(
        "mma.sync.aligned.m16n8k8.row.col.f32.tf32.tf32.f32 "
        "{%0,%1,%2,%3}, {%4,%5,%6,%7}, {%8,%9}, {%0,%1,%2,%3};\n"
        : "+f"(c[0]), "+f"(c[1]), "+f"(c[2]), "+f"(c[3])
        : "r"(a0), "r"(a1), "r"(a2), "r"(a3), "r"(b0), "r"(b1));
}

// GEMM smem geometry: A row-major [128][36], B [32][136], double buffered.
#define AP   36
#define BP   136
#define ASZ  (128 * AP)
#define BSZ  (32 * BP)
#define GEMM_SMEM_BYTES ((2 * ASZ + 2 * BSZ) * 4)   // 71680

// ============================================================================
// GEMM core (exact R5 design — local optimum, do not touch).
// ============================================================================
struct GemmCore {
    template <bool ROPE_EPI>
    static __device__ __forceinline__ void run(
        const float* __restrict__ A, const float* __restrict__ B,
        float* __restrict__ C, const float* __restrict__ F,
        int N, int K, int mbase, int nbase_local) {

        extern __shared__ unsigned smg[];
        unsigned* AsBuf = smg;
        unsigned* BsBuf = smg + 2 * ASZ;

        const int tid  = threadIdx.x;
        const int lane = tid & 31;
        const int warp = tid >> 5;
        const int m0w = (warp >> 1) * 64;
        const int n0w = (warp & 1) * 64;
        const int qr = lane >> 2, qc = lane & 3;

        float acc[4][8][4];
#pragma unroll
        for (int mt = 0; mt < 4; ++mt)
#pragma unroll
            for (int nt = 0; nt < 8; ++nt)
#pragma unroll
                for (int j = 0; j < 4; ++j) acc[mt][nt][j] = 0.f;

        const int arow = tid >> 3, af4 = tid & 7;
        const int brow = tid >> 5, bf4 = tid & 31;

        float4 pa[8], pb[8];

#pragma unroll
        for (int i = 0; i < 8; ++i)
            pa[i] = *(const float4*)&A[(size_t)(mbase + arow + i * 16) * K + af4 * 4];
#pragma unroll
        for (int i = 0; i < 8; ++i)
            pb[i] = *(const float4*)&B[(size_t)(brow + i * 4) * N + nbase_local + bf4 * 4];
#pragma unroll
        for (int i = 0; i < 8; ++i) {
            int r = arow + i * 16;
            uint4 u = make_uint4(f2t(pa[i].x), f2t(pa[i].y), f2t(pa[i].z), f2t(pa[i].w));
            *(uint4*)&AsBuf[r * AP + af4 * 4] = u;
        }
#pragma unroll
        for (int i = 0; i < 8; ++i) {
            int r = brow + i * 4;
            uint4 u = make_uint4(f2t(pb[i].x), f2t(pb[i].y), f2t(pb[i].z), f2t(pb[i].w));
            *(uint4*)&BsBuf[r * BP + bf4 * 4] = u;
        }
        if (32 < K) {
#pragma unroll
            for (int i = 0; i < 8; ++i)
                pa[i] = *(const float4*)&A[(size_t)(mbase + arow + i * 16) * K + 32 + af4 * 4];
#pragma unroll
            for (int i = 0; i < 8; ++i)
                pb[i] = *(const float4*)&B[(size_t)(32 + brow + i * 4) * N + nbase_local + bf4 * 4];
        }
        __syncthreads();

        int buf = 0;
        for (int kb = 0; kb < K; kb += 32) {
            unsigned* Asb = AsBuf + buf * ASZ;
            unsigned* Bsb = BsBuf + buf * BSZ;

            if (kb + 32 < K) {
                unsigned* Asn = AsBuf + (buf ^ 1) * ASZ;
                unsigned* Bsn = BsBuf + (buf ^ 1) * BSZ;
#pragma unroll
                for (int i = 0; i < 8; ++i) {
                    int r = arow + i * 16;
                    uint4 u = make_uint4(f2t(pa[i].x), f2t(pa[i].y), f2t(pa[i].z), f2t(pa[i].w));
                    *(uint4*)&Asn[r * AP + af4 * 4] = u;
                }
#pragma unroll
                for (int i = 0; i < 8; ++i) {
                    int r = brow + i * 4;
                    uint4 u = make_uint4(f2t(pb[i].x), f2t(pb[i].y), f2t(pb[i].z), f2t(pb[i].w));
                    *(uint4*)&Bsn[r * BP + bf4 * 4] = u;
                }
            }
            if (kb + 64 < K) {
#pragma unroll
                for (int i = 0; i < 8; ++i)
                    pa[i] = *(const float4*)&A[(size_t)(mbase + arow + i * 16) * K + kb + 64 + af4 * 4];
#pragma unroll
                for (int i = 0; i < 8; ++i)
                    pb[i] = *(const float4*)&B[(size_t)(kb + 64 + brow + i * 4) * N + nbase_local + bf4 * 4];
            }

#pragma unroll
            for (int ks = 0; ks < 4; ++ks) {
                const int k0 = ks * 8;
                unsigned a[4][4];
#pragma unroll
                for (int mt = 0; mt < 4; ++mt) {
                    int m = m0w + mt * 16;
                    a[mt][0] = Asb[(m + qr) * AP + k0 + qc];
                    a[mt][1] = Asb[(m + 8 + qr) * AP + k0 + qc];
                    a[mt][2] = Asb[(m + qr) * AP + k0 + 4 + qc];
                    a[mt][3] = Asb[(m + 8 + qr) * AP + k0 + 4 + qc];
                }
#pragma unroll
                for (int nt = 0; nt < 8; ++nt) {
                    int n = n0w + nt * 8;
                    unsigned b0 = Bsb[(k0 + qc) * BP + n + qr];
                    unsigned b1 = Bsb[(k0 + 4 + qc) * BP + n + qr];
#pragma unroll
                    for (int mt = 0; mt < 4; ++mt)
                        mma_tf32(acc[mt][nt], a[mt][0], a[mt][1], a[mt][2], a[mt][3], b0, b1);
                }
            }
            __syncthreads();
            buf ^= 1;
        }

#pragma unroll
        for (int mt = 0; mt < 4; ++mt) {
#pragma unroll
            for (int nt = 0; nt < 8; ++nt) {
                int row = mbase + m0w + mt * 16 + qr;
                int lcol = nbase_local + n0w + nt * 8 + 2 * qc;
                float2 v0 = make_float2(acc[mt][nt][0], acc[mt][nt][1]);
                float2 v1 = make_float2(acc[mt][nt][2], acc[mt][nt][3]);
                if (ROPE_EPI) {
                    int d = lcol & 63;
                    float2 f0 = *(const float2*)&F[(size_t)row * 64 + d];
                    float2 f1 = *(const float2*)&F[(size_t)(row + 8) * 64 + d];
                    v0 = make_float2(v0.x * f0.x - v0.y * f0.y, v0.x * f0.y + v0.y * f0.x);
                    v1 = make_float2(v1.x * f1.x - v1.y * f1.y, v1.x * f1.y + v1.y * f1.x);
                }
                *(float2*)&C[(size_t)row * N + lcol] = v0;
                *(float2*)&C[(size_t)(row + 8) * N + lcol] = v1;
            }
        }
    }
};

__global__ __launch_bounds__(128)
void qkv_gemm_kernel(const float* __restrict__ A,
                     const float* __restrict__ Wq,
                     const float* __restrict__ Wk,
                     const float* __restrict__ Wv,
                     const float* __restrict__ F,
                     float* __restrict__ Qp,
                     float* __restrict__ Kp,
                     float* __restrict__ Vp) {
    const int mbase = blockIdx.y * 128;
    const int nbase = blockIdx.x * 128;
    if (nbase < QSTRIDE) {
        GemmCore::run<true>(A, Wq, Qp, F, QSTRIDE, E, mbase, nbase);
    } else if (nbase < QSTRIDE + KSTRIDE) {
        GemmCore::run<true>(A, Wk, Kp, F, KSTRIDE, E, mbase, nbase - QSTRIDE);
    } else {
        GemmCore::run<false>(A, Wv, Vp, nullptr, KSTRIDE, E, mbase,
                             nbase - QSTRIDE - KSTRIDE);
    }
}

__global__ __launch_bounds__(128)
void tgemm_kernel(const float* __restrict__ A,
                  const float* __restrict__ B,
                  float* __restrict__ C,
                  int M, int N, int K) {
    GemmCore::run<false>(A, B, C, nullptr, N, K, blockIdx.y * 128, blockIdx.x * 128);
}

// ============================================================================
// GQA-shared TF32 flash attention + double-buffered K/V (register prefetch).
// CTA = 64 seq rows x 4 q-heads of one kv-head; 256 threads, 8 warps, all
// consumers AND cooperative loaders (8 float4 prefetch regs/thread).
// ONE __syncthreads per kt iteration.
// ============================================================================
#define FPQ 68
#define FPV 72
#define KVB (64 * FPQ)        // words per K buffer
#define VVB (64 * FPV)        // words per V buffer
#define FA_SMEM_WORDS (256*FPQ + 2*KVB + 2*VVB + 256*FPQ)
#define FA_SMEM_BYTES (FA_SMEM_WORDS * 4)   // 206848

__global__ __launch_bounds__(256)
void flash_gqa_kernel(const float* __restrict__ Q,
                      const float* __restrict__ Kg,
                      const float* __restrict__ Vg,
                      float* __restrict__ O) {
    const int kh = blockIdx.y;                       // kv head 0..7
    const int qt = (gridDim.x - 1) - blockIdx.x;     // heavy tiles first
    const int qbase = qt * 64;

    extern __shared__ unsigned smu[];
    unsigned* Qs  = smu;                  // [256][FPQ]  row = h_local*64 + seq
    unsigned* Ks0 = Qs + 256 * FPQ;       // 2 x [64][FPQ]
    unsigned* Vs0 = Ks0 + 2 * KVB;        // 2 x [64][FPV]
    unsigned* Ps  = Vs0 + 2 * VVB;        // [256][FPQ]

    const int tid = threadIdx.x;
    const int lane = tid & 31;
    const int warp = tid >> 5;
    const int h_local = warp >> 1;                   // 0..3
    const int h = kh * 4 + h_local;                  // global q head
    const int m0q = (warp & 1) * 32;                 // seq offset within tile
    const int prow = h_local * 64 + m0q;             // base row in Qs/Ps
    const int qr = lane >> 2;
    const int qc = lane & 3;
    const int f4 = tid & 15;
    const int row0 = tid >> 4;                       // 0..15

    // ---- load Q: 256 rows (4 heads x 64 seq) x 16 f4 ----
#pragma unroll
    for (int i = 0; i < 16; ++i) {
        int r = row0 + i * 16;
        int hl = r >> 6;
        int sr = r & 63;
        float4 v = *(const float4*)&Q[(size_t)(qbase + sr) * QSTRIDE
                                      + (kh * 4 + hl) * D + f4 * 4];
        uint4 u = make_uint4(f2t(v.x), f2t(v.y), f2t(v.z), f2t(v.w));
        *(uint4*)&Qs[r * FPQ + f4 * 4] = u;
    }

    float o[2][8][4];
#pragma unroll
    for (int mt = 0; mt < 2; ++mt)
#pragma unroll
        for (int nt = 0; nt < 8; ++nt)
#pragma unroll
            for (int j = 0; j < 4; ++j) o[mt][nt][j] = 0.f;
    float mr[2][2], lr[2][2];
#pragma unroll
    for (int mt = 0; mt < 2; ++mt) {
        mr[mt][0] = -1e30f; mr[mt][1] = -1e30f;
        lr[mt][0] = 0.f;    lr[mt][1] = 0.f;
    }

    // prefetch tile 0 into registers (4 f4 K + 4 f4 V per thread)
    float4 pk[4], pv[4];
#pragma unroll
    for (int i = 0; i < 4; ++i) {
        int r = row0 + i * 16;
        pk[i] = *(const float4*)&Kg[(size_t)r * KSTRIDE + kh * D + f4 * 4];
        pv[i] = *(const float4*)&Vg[(size_t)r * KSTRIDE + kh * D + f4 * 4];
    }

    for (int kt = 0; kt <= qt; ++kt) {
        const int kbase = kt * 64;
        const int p = kt & 1;
        unsigned* Ksb = Ks0 + p * KVB;
        unsigned* Vsb = Vs0 + p * VVB;

        // store prefetched tile kt (ordered after iter kt-2 reads by
        // iter kt-1's barrier)
#pragma unroll
        for (int i = 0; i < 4; ++i) {
            int r = row0 + i * 16;
            uint4 uk = make_uint4(f2t(pk[i].x), f2t(pk[i].y), f2t(pk[i].z), f2t(pk[i].w));
            *(uint4*)&Ksb[r * FPQ + f4 * 4] = uk;
            uint4 uv = make_uint4(f2t(pv[i].x), f2t(pv[i].y), f2t(pv[i].z), f2t(pv[i].w));
            *(uint4*)&Vsb[r * FPV + f4 * 4] = uv;
        }
        __syncthreads();   // publish tile kt

        // prefetch tile kt+1 (LDG latency hides under compute below)
        if (kt < qt) {
            const int nb = (kt + 1) * 64;
#pragma unroll
            for (int i = 0; i < 4; ++i) {
                int r = nb + row0 + i * 16;
                pk[i] = *(const float4*)&Kg[(size_t)r * KSTRIDE + kh * D + f4 * 4];
                pv[i] = *(const float4*)&Vg[(size_t)r * KSTRIDE + kh * D + f4 * 4];
            }
        }

        // ---- S = Q K^T ----
        float s[2][8][4];
#pragma unroll
        for (int mt = 0; mt < 2; ++mt)
#pragma unroll
            for (int nt = 0; nt < 8; ++nt)
#pragma unroll
                for (int j = 0; j < 4; ++j) s[mt][nt][j] = 0.f;

#pragma unroll
        for (int ks = 0; ks < 8; ++ks) {
            const int k0 = ks * 8;
            unsigned a[2][4];
#pragma unroll
            for (int mt = 0; mt < 2; ++mt) {
                int m = prow + mt * 16;
                a[mt][0] = Qs[(m + qr) * FPQ + k0 + qc];
                a[mt][1] = Qs[(m + 8 + qr) * FPQ + k0 + qc];
                a[mt][2] = Qs[(m + qr) * FPQ + k0 + 4 + qc];
                a[mt][3] = Qs[(m + 8 + qr) * FPQ + k0 + 4 + qc];
            }
#pragma unroll
            for (int nt = 0; nt < 8; ++nt) {
                unsigned b0 = Ksb[(nt * 8 + qr) * FPQ + k0 + qc];
                unsigned b1 = Ksb[(nt * 8 + qr) * FPQ + k0 + 4 + qc];
#pragma unroll
                for (int mt = 0; mt < 2; ++mt)
                    mma_tf32(s[mt][nt], a[mt][0], a[mt][1], a[mt][2], a[mt][3], b0, b1);
            }
        }

        // ---- scale + causal mask + online softmax (per mt) ----
        const bool diag = (kt == qt);
#pragma unroll
        for (int mt = 0; mt < 2; ++mt) {
            const int q_lo = qbase + m0q + mt * 16 + qr;
            const int q_hi = q_lo + 8;
#pragma unroll
            for (int nt = 0; nt < 8; ++nt) {
#pragma unroll
                for (int j = 0; j < 2; ++j) {
                    int kcol = kbase + nt * 8 + 2 * qc + j;
                    float v0 = s[mt][nt][j] * 0.125f;
                    float v1 = s[mt][nt][2 + j] * 0.125f;
                    if (diag && kcol > q_lo) v0 = -1e30f;
                    if (diag && kcol > q_hi) v1 = -1e30f;
                    s[mt][nt][j] = v0;
                    s[mt][nt][2 + j] = v1;
                }
            }

            float tm_lo = -1e30f, tm_hi = -1e30f;
#pragma unroll
            for (int nt = 0; nt < 8; ++nt) {
                tm_lo = fmaxf(tm_lo, fmaxf(s[mt][nt][0], s[mt][nt][1]));
                tm_hi = fmaxf(tm_hi, fmaxf(s[mt][nt][2], s[mt][nt][3]));
            }
#pragma unroll
            for (int off = 1; off <= 2; off <<= 1) {
                tm_lo = fmaxf(tm_lo, __shfl_xor_sync(0xffffffffu, tm_lo, off));
                tm_hi = fmaxf(tm_hi, __shfl_xor_sync(0xffffffffu, tm_hi, off));
            }
            float mn_lo = fmaxf(mr[mt][0], tm_lo);
            float mn_hi = fmaxf(mr[mt][1], tm_hi);
            float fac_lo = __expf(mr[mt][0] - mn_lo);
            float fac_hi = __expf(mr[mt][1] - mn_hi);

            float sum_lo = 0.f, sum_hi = 0.f;
#pragma unroll
            for (int nt = 0; nt < 8; ++nt) {
                float p0 = __expf(s[mt][nt][0] - mn_lo);
                float p1 = __expf(s[mt][nt][1] - mn_lo);
                float p2 = __expf(s[mt][nt][2] - mn_hi);
                float p3 = __expf(s[mt][nt][3] - mn_hi);
                s[mt][nt][0] = p0; s[mt][nt][1] = p1;
                s[mt][nt][2] = p2; s[mt][nt][3] = p3;
                sum_lo += p0 + p1;
                sum_hi += p2 + p3;
            }
#pragma unroll
            for (int off = 1; off <= 2; off <<= 1) {
                sum_lo += __shfl_xor_sync(0xffffffffu, sum_lo, off);
                sum_hi += __shfl_xor_sync(0xffffffffu, sum_hi, off);
            }
            lr[mt][0] = lr[mt][0] * fac_lo + sum_lo;
            lr[mt][1] = lr[mt][1] * fac_hi + sum_hi;
            mr[mt][0] = mn_lo;
            mr[mt][1] = mn_hi;

#pragma unroll
            for (int nt = 0; nt < 8; ++nt) {
                o[mt][nt][0] *= fac_lo; o[mt][nt][1] *= fac_lo;
                o[mt][nt][2] *= fac_hi; o[mt][nt][3] *= fac_hi;
            }

            // write P fragments to smem (warp-private rows)
#pragma unroll
            for (int nt = 0; nt < 8; ++nt) {
                int r = prow + mt * 16 + qr;
                int c = nt * 8 + 2 * qc;
                Ps[r * FPQ + c]           = f2t(s[mt][nt][0]);
                Ps[r * FPQ + c + 1]       = f2t(s[mt][nt][1]);
                Ps[(r + 8) * FPQ + c]     = f2t(s[mt][nt][2]);
                Ps[(r + 8) * FPQ + c + 1] = f2t(s[mt][nt][3]);
            }
        }
        __syncwarp();

        // ---- O += P V ----
#pragma unroll
        for (int ks = 0; ks < 8; ++ks) {
            const int k0 = ks * 8;
            unsigned a[2][4];
#pragma unroll
            for (int mt = 0; mt < 2; ++mt) {
                int m = prow + mt * 16;
                a[mt][0] = Ps[(m + qr) * FPQ + k0 + qc];
                a[mt][1] = Ps[(m + 8 + qr) * FPQ + k0 + qc];
                a[mt][2] = Ps[(m + qr) * FPQ + k0 + 4 + qc];
                a[mt][3] = Ps[(m + 8 + qr) * FPQ + k0 + 4 + qc];
            }
#pragma unroll
            for (int nt = 0; nt < 8; ++nt) {
                unsigned b0 = Vsb[(k0 + qc) * FPV + nt * 8 + qr];
                unsigned b1 = Vsb[(k0 + 4 + qc) * FPV + nt * 8 + qr];
#pragma unroll
                for (int mt = 0; mt < 2; ++mt)
                    mma_tf32(o[mt][nt], a[mt][0], a[mt][1], a[mt][2], a[mt][3], b0, b1);
            }
        }
    }

    // ---- normalize + write out ----
#pragma unroll
    for (int mt = 0; mt < 2; ++mt) {
        float inv_lo = 1.f / lr[mt][0];
        float inv_hi = 1.f / lr[mt][1];
#pragma unroll
        for (int nt = 0; nt < 8; ++nt) {
            int row = qbase + m0q + mt * 16 + qr;
            int col = h * D + nt * 8 + 2 * qc;
            *(float2*)&O[(size_t)row * QSTRIDE + col] =
                make_float2(o[mt][nt][0] * inv_lo, o[mt][nt][1] * inv_lo);
            *(float2*)&O[(size_t)(row + 8) * QSTRIDE + col] =
                make_float2(o[mt][nt][2] * inv_hi, o[mt][nt][3] * inv_hi);
        }
    }
}

// ---------------- launch ---------------------------------------------------
extern "C" void kernel_launch(void* const* d_in, const int* in_sizes, int n_in,
                              void* d_out, int out_size) {
    const float* x  = (const float*)d_in[0];
    const float* fc = (const float*)d_in[1];
    const float* Wq = (const float*)d_in[3];
    const float* Wk = (const float*)d_in[4];
    const float* Wv = (const float*)d_in[5];
    const float* Wo = (const float*)d_in[6];
    float* out = (float*)d_out;

    float *Q, *K, *V, *A;
    cudaGetSymbolAddress((void**)&Q, g_Q);
    cudaGetSymbolAddress((void**)&K, g_K);
    cudaGetSymbolAddress((void**)&V, g_V);
    cudaGetSymbolAddress((void**)&A, g_A);

    cudaFuncSetAttribute(qkv_gemm_kernel,
                         cudaFuncAttributeMaxDynamicSharedMemorySize, GEMM_SMEM_BYTES);
    cudaFuncSetAttribute(tgemm_kernel,
                         cudaFuncAttributeMaxDynamicSharedMemorySize, GEMM_SMEM_BYTES);
    cudaFuncSetAttribute(flash_gqa_kernel,
                         cudaFuncAttributeMaxDynamicSharedMemorySize, FA_SMEM_BYTES);

    // fused QKV projection + RoPE (Q,K only)
    qkv_gemm_kernel<<<dim3(NTOT / 128, S / 128), 128, GEMM_SMEM_BYTES>>>(
        x, Wq, Wk, Wv, fc, Q, K, V);

    // GQA-shared causal flash attention, double-buffered K/V
    flash_gqa_kernel<<<dim3(S / 64, HKV), 256, FA_SMEM_BYTES>>>(Q, K, V, A);

    // output projection
    tgemm_kernel<<<dim3(E / 128, S / 128), 128, GEMM_SMEM_BYTES>>>(A, Wo, out, S, E, E);
}

// round 15
// speedup vs baseline: 1.2663x; 1.0524x over previous
#include <cuda_runtime.h>
#include <cuda_bf16.h>
#include <cstdint>

// Problem constants
#define S      2048
#define E      2048
#define HQ     32
#define HKV    8
#define D      64
#define QSTRIDE (HQ*D)    // 2048
#define KSTRIDE (HKV*D)   // 512
#define NTOT   (QSTRIDE + 2*KSTRIDE)  // 3072

// ---------------- scratch (device globals; no allocation allowed) ----------
__device__ float g_Q[S * QSTRIDE];
__device__ float g_K[S * KSTRIDE];
__device__ float g_V[S * KSTRIDE];
__device__ float g_A[S * QSTRIDE];

// ---------------- helpers ---------------------------------------------------
__device__ __forceinline__ unsigned f2t(float f) {
    unsigned u;
    asm("cvt.rna.tf32.f32 %0, %1;" : "=r"(u) : "f"(f));
    return u;
}

__device__ __forceinline__ void mma_tf32(float c[4],
                                         unsigned a0, unsigned a1, unsigned a2, unsigned a3,
                                         unsigned b0, unsigned b1) {
    asm volatile(
        "mma.sync.aligned.m16n8k8.row.col.f32.tf32.tf32.f32 "
        "{%0,%1,%2,%3}, {%4,%5,%6,%7}, {%8,%9}, {%0,%1,%2,%3};\n"
        : "+f"(c[0]), "+f"(c[1]), "+f"(c[2]), "+f"(c[3])
        : "r"(a0), "r"(a1), "r"(a2), "r"(a3), "r"(b0), "r"(b1));
}

// GEMM smem geometry: A row-major [128][36], B [32][136], double buffered.
#define AP   36
#define BP   136
#define ASZ  (128 * AP)
#define BSZ  (32 * BP)
#define GEMM_SMEM_BYTES ((2 * ASZ + 2 * BSZ) * 4)   // 71680

// ============================================================================
// GEMM core (exact R5 design — local optimum, do not touch).
// ============================================================================
struct GemmCore {
    template <bool ROPE_EPI>
    static __device__ __forceinline__ void run(
        const float* __restrict__ A, const float* __restrict__ B,
        float* __restrict__ C, const float* __restrict__ F,
        int N, int K, int mbase, int nbase_local) {

        extern __shared__ unsigned smg[];
        unsigned* AsBuf = smg;
        unsigned* BsBuf = smg + 2 * ASZ;

        const int tid  = threadIdx.x;
        const int lane = tid & 31;
        const int warp = tid >> 5;
        const int m0w = (warp >> 1) * 64;
        const int n0w = (warp & 1) * 64;
        const int qr = lane >> 2, qc = lane & 3;

        float acc[4][8][4];
#pragma unroll
        for (int mt = 0; mt < 4; ++mt)
#pragma unroll
            for (int nt = 0; nt < 8; ++nt)
#pragma unroll
                for (int j = 0; j < 4; ++j) acc[mt][nt][j] = 0.f;

        const int arow = tid >> 3, af4 = tid & 7;
        const int brow = tid >> 5, bf4 = tid & 31;

        float4 pa[8], pb[8];

#pragma unroll
        for (int i = 0; i < 8; ++i)
            pa[i] = *(const float4*)&A[(size_t)(mbase + arow + i * 16) * K + af4 * 4];
#pragma unroll
        for (int i = 0; i < 8; ++i)
            pb[i] = *(const float4*)&B[(size_t)(brow + i * 4) * N + nbase_local + bf4 * 4];
#pragma unroll
        for (int i = 0; i < 8; ++i) {
            int r = arow + i * 16;
            uint4 u = make_uint4(f2t(pa[i].x), f2t(pa[i].y), f2t(pa[i].z), f2t(pa[i].w));
            *(uint4*)&AsBuf[r * AP + af4 * 4] = u;
        }
#pragma unroll
        for (int i = 0; i < 8; ++i) {
            int r = brow + i * 4;
            uint4 u = make_uint4(f2t(pb[i].x), f2t(pb[i].y), f2t(pb[i].z), f2t(pb[i].w));
            *(uint4*)&BsBuf[r * BP + bf4 * 4] = u;
        }
        if (32 < K) {
#pragma unroll
            for (int i = 0; i < 8; ++i)
                pa[i] = *(const float4*)&A[(size_t)(mbase + arow + i * 16) * K + 32 + af4 * 4];
#pragma unroll
            for (int i = 0; i < 8; ++i)
                pb[i] = *(const float4*)&B[(size_t)(32 + brow + i * 4) * N + nbase_local + bf4 * 4];
        }
        __syncthreads();

        int buf = 0;
        for (int kb = 0; kb < K; kb += 32) {
            unsigned* Asb = AsBuf + buf * ASZ;
            unsigned* Bsb = BsBuf + buf * BSZ;

            if (kb + 32 < K) {
                unsigned* Asn = AsBuf + (buf ^ 1) * ASZ;
                unsigned* Bsn = BsBuf + (buf ^ 1) * BSZ;
#pragma unroll
                for (int i = 0; i < 8; ++i) {
                    int r = arow + i * 16;
                    uint4 u = make_uint4(f2t(pa[i].x), f2t(pa[i].y), f2t(pa[i].z), f2t(pa[i].w));
                    *(uint4*)&Asn[r * AP + af4 * 4] = u;
                }
#pragma unroll
                for (int i = 0; i < 8; ++i) {
                    int r = brow + i * 4;
                    uint4 u = make_uint4(f2t(pb[i].x), f2t(pb[i].y), f2t(pb[i].z), f2t(pb[i].w));
                    *(uint4*)&Bsn[r * BP + bf4 * 4] = u;
                }
            }
            if (kb + 64 < K) {
#pragma unroll
                for (int i = 0; i < 8; ++i)
                    pa[i] = *(const float4*)&A[(size_t)(mbase + arow + i * 16) * K + kb + 64 + af4 * 4];
#pragma unroll
                for (int i = 0; i < 8; ++i)
                    pb[i] = *(const float4*)&B[(size_t)(kb + 64 + brow + i * 4) * N + nbase_local + bf4 * 4];
            }

#pragma unroll
            for (int ks = 0; ks < 4; ++ks) {
                const int k0 = ks * 8;
                unsigned a[4][4];
#pragma unroll
                for (int mt = 0; mt < 4; ++mt) {
                    int m = m0w + mt * 16;
                    a[mt][0] = Asb[(m + qr) * AP + k0 + qc];
                    a[mt][1] = Asb[(m + 8 + qr) * AP + k0 + qc];
                    a[mt][2] = Asb[(m + qr) * AP + k0 + 4 + qc];
                    a[mt][3] = Asb[(m + 8 + qr) * AP + k0 + 4 + qc];
                }
#pragma unroll
                for (int nt = 0; nt < 8; ++nt) {
                    int n = n0w + nt * 8;
                    unsigned b0 = Bsb[(k0 + qc) * BP + n + qr];
                    unsigned b1 = Bsb[(k0 + 4 + qc) * BP + n + qr];
#pragma unroll
                    for (int mt = 0; mt < 4; ++mt)
                        mma_tf32(acc[mt][nt], a[mt][0], a[mt][1], a[mt][2], a[mt][3], b0, b1);
                }
            }
            __syncthreads();
            buf ^= 1;
        }

#pragma unroll
        for (int mt = 0; mt < 4; ++mt) {
#pragma unroll
            for (int nt = 0; nt < 8; ++nt) {
                int row = mbase + m0w + mt * 16 + qr;
                int lcol = nbase_local + n0w + nt * 8 + 2 * qc;
                float2 v0 = make_float2(acc[mt][nt][0], acc[mt][nt][1]);
                float2 v1 = make_float2(acc[mt][nt][2], acc[mt][nt][3]);
                if (ROPE_EPI) {
                    int d = lcol & 63;
                    float2 f0 = *(const float2*)&F[(size_t)row * 64 + d];
                    float2 f1 = *(const float2*)&F[(size_t)(row + 8) * 64 + d];
                    v0 = make_float2(v0.x * f0.x - v0.y * f0.y, v0.x * f0.y + v0.y * f0.x);
                    v1 = make_float2(v1.x * f1.x - v1.y * f1.y, v1.x * f1.y + v1.y * f1.x);
                }
                *(float2*)&C[(size_t)row * N + lcol] = v0;
                *(float2*)&C[(size_t)(row + 8) * N + lcol] = v1;
            }
        }
    }
};

__global__ __launch_bounds__(128)
void qkv_gemm_kernel(const float* __restrict__ A,
                     const float* __restrict__ Wq,
                     const float* __restrict__ Wk,
                     const float* __restrict__ Wv,
                     const float* __restrict__ F,
                     float* __restrict__ Qp,
                     float* __restrict__ Kp,
                     float* __restrict__ Vp) {
    const int mbase = blockIdx.y * 128;
    const int nbase = blockIdx.x * 128;
    if (nbase < QSTRIDE) {
        GemmCore::run<true>(A, Wq, Qp, F, QSTRIDE, E, mbase, nbase);
    } else if (nbase < QSTRIDE + KSTRIDE) {
        GemmCore::run<true>(A, Wk, Kp, F, KSTRIDE, E, mbase, nbase - QSTRIDE);
    } else {
        GemmCore::run<false>(A, Wv, Vp, nullptr, KSTRIDE, E, mbase,
                             nbase - QSTRIDE - KSTRIDE);
    }
}

__global__ __launch_bounds__(128)
void tgemm_kernel(const float* __restrict__ A,
                  const float* __restrict__ B,
                  float* __restrict__ C,
                  int M, int N, int K) {
    GemmCore::run<false>(A, B, C, nullptr, N, K, blockIdx.y * 128, blockIdx.x * 128);
}

// ============================================================================
// TF32 flash attention (R5 base): 128 q-rows/CTA, 4 warps x 32 rows
// (mt=2, nt=8). CHANGES vs R5: Q fragments hoisted to registers once
// (loop-invariant, -64 LDS/iter); Ps overlaid on Qs (smem 105.5 -> 70.7 KB);
// __launch_bounds__(128, 2) to pin 2 CTAs/SM.
// ============================================================================
#define FPQ 68
#define FPV 72
#define FA_SMEM_WORDS (128*FPQ + 64*FPQ + 64*FPV)   // QsPs + Ks + Vs
#define FA_SMEM_BYTES (FA_SMEM_WORDS * 4)            // 70656

__global__ __launch_bounds__(128, 2)
void flash_tc_kernel(const float* __restrict__ Q,
                     const float* __restrict__ Kg,
                     const float* __restrict__ Vg,
                     float* __restrict__ O) {
    const int h = blockIdx.y;
    const int qt = (gridDim.x - 1) - blockIdx.x;
    const int qbase = qt * 128;
    const int kh = h >> 2;

    extern __shared__ unsigned smu[];
    unsigned* QsPs = smu;                  // [128][FPQ]  Q tile, then P
    unsigned* Ks   = QsPs + 128 * FPQ;     // [64][FPQ]
    unsigned* Vs   = Ks + 64 * FPQ;        // [64][FPV] row-major [k][d]

    const int tid = threadIdx.x;
    const int lane = tid & 31;
    const int warp = tid >> 5;
    const int m0 = warp * 32;
    const int qr = lane >> 2;
    const int qc = lane & 3;
    const int f4 = tid & 15;
    const int row0 = tid >> 4;

    // ---- load Q tile (128 x 64) ----
#pragma unroll
    for (int i = 0; i < 16; ++i) {
        int r = row0 + i * 8;
        float4 v = *(const float4*)&Q[(size_t)(qbase + r) * QSTRIDE + h * D + f4 * 4];
        uint4 u = make_uint4(f2t(v.x), f2t(v.y), f2t(v.z), f2t(v.w));
        *(uint4*)&QsPs[r * FPQ + f4 * 4] = u;
    }
    __syncthreads();

    // ---- hoist Q fragments (loop-invariant) into registers ----
    unsigned qa[8][2][4];
#pragma unroll
    for (int ks = 0; ks < 8; ++ks) {
        const int k0 = ks * 8;
#pragma unroll
        for (int mt = 0; mt < 2; ++mt) {
            int m = m0 + mt * 16;
            qa[ks][mt][0] = QsPs[(m + qr) * FPQ + k0 + qc];
            qa[ks][mt][1] = QsPs[(m + 8 + qr) * FPQ + k0 + qc];
            qa[ks][mt][2] = QsPs[(m + qr) * FPQ + k0 + 4 + qc];
            qa[ks][mt][3] = QsPs[(m + 8 + qr) * FPQ + k0 + 4 + qc];
        }
    }
    // From here on, QsPs serves as the P buffer (warp-private rows).

    float o[2][8][4];
#pragma unroll
    for (int mt = 0; mt < 2; ++mt)
#pragma unroll
        for (int nt = 0; nt < 8; ++nt)
#pragma unroll
            for (int j = 0; j < 4; ++j) o[mt][nt][j] = 0.f;
    float mr[2][2], lr[2][2];
#pragma unroll
    for (int mt = 0; mt < 2; ++mt) {
        mr[mt][0] = -1e30f; mr[mt][1] = -1e30f;
        lr[mt][0] = 0.f;    lr[mt][1] = 0.f;
    }

    const int kt_max = 2 * qt + 1;
    for (int kt = 0; kt <= kt_max; ++kt) {
        __syncthreads();   // prior iteration's K/V (and P) reads complete;
                           // also orders Q-frag extraction before P writes
        const int kbase = kt * 64;

        // load K tile (64 x 64)
#pragma unroll
        for (int i = 0; i < 8; ++i) {
            int r = row0 + i * 8;
            float4 v = *(const float4*)&Kg[(size_t)(kbase + r) * KSTRIDE + kh * D + f4 * 4];
            uint4 u = make_uint4(f2t(v.x), f2t(v.y), f2t(v.z), f2t(v.w));
            *(uint4*)&Ks[r * FPQ + f4 * 4] = u;
        }
        // load V tile (64 x 64) row-major [k][d]
#pragma unroll
        for (int i = 0; i < 8; ++i) {
            int r = row0 + i * 8;
            float4 v = *(const float4*)&Vg[(size_t)(kbase + r) * KSTRIDE + kh * D + f4 * 4];
            uint4 u = make_uint4(f2t(v.x), f2t(v.y), f2t(v.z), f2t(v.w));
            *(uint4*)&Vs[r * FPV + f4 * 4] = u;
        }
        __syncthreads();

        if (kbase > qbase + m0 + 31) continue;

        // ---- S = Q K^T (Q fragments from registers) ----
        float s[2][8][4];
#pragma unroll
        for (int mt = 0; mt < 2; ++mt)
#pragma unroll
            for (int nt = 0; nt < 8; ++nt)
#pragma unroll
                for (int j = 0; j < 4; ++j) s[mt][nt][j] = 0.f;

#pragma unroll
        for (int ks = 0; ks < 8; ++ks) {
            const int k0 = ks * 8;
#pragma unroll
            for (int nt = 0; nt < 8; ++nt) {
                unsigned b0 = Ks[(nt * 8 + qr) * FPQ + k0 + qc];
                unsigned b1 = Ks[(nt * 8 + qr) * FPQ + k0 + 4 + qc];
#pragma unroll
                for (int mt = 0; mt < 2; ++mt)
                    mma_tf32(s[mt][nt], qa[ks][mt][0], qa[ks][mt][1],
                             qa[ks][mt][2], qa[ks][mt][3], b0, b1);
            }
        }

        // ---- scale + causal mask + online softmax (per mt) ----
#pragma unroll
        for (int mt = 0; mt < 2; ++mt) {
            const int q_lo = qbase + m0 + mt * 16 + qr;
            const int q_hi = q_lo + 8;
            const bool need_mask = (kbase + 63 > q_lo);
#pragma unroll
            for (int nt = 0; nt < 8; ++nt) {
#pragma unroll
                for (int j = 0; j < 2; ++j) {
                    int kcol = kbase + nt * 8 + 2 * qc + j;
                    float v0 = s[mt][nt][j] * 0.125f;
                    float v1 = s[mt][nt][2 + j] * 0.125f;
                    if (need_mask && kcol > q_lo) v0 = -1e30f;
                    if (need_mask && kcol > q_hi) v1 = -1e30f;
                    s[mt][nt][j] = v0;
                    s[mt][nt][2 + j] = v1;
                }
            }

            float tm_lo = -1e30f, tm_hi = -1e30f;
#pragma unroll
            for (int nt = 0; nt < 8; ++nt) {
                tm_lo = fmaxf(tm_lo, fmaxf(s[mt][nt][0], s[mt][nt][1]));
                tm_hi = fmaxf(tm_hi, fmaxf(s[mt][nt][2], s[mt][nt][3]));
            }
#pragma unroll
            for (int off = 1; off <= 2; off <<= 1) {
                tm_lo = fmaxf(tm_lo, __shfl_xor_sync(0xffffffffu, tm_lo, off));
                tm_hi = fmaxf(tm_hi, __shfl_xor_sync(0xffffffffu, tm_hi, off));
            }
            float mn_lo = fmaxf(mr[mt][0], tm_lo);
            float mn_hi = fmaxf(mr[mt][1], tm_hi);
            float fac_lo = __expf(mr[mt][0] - mn_lo);
            float fac_hi = __expf(mr[mt][1] - mn_hi);

            float sum_lo = 0.f, sum_hi = 0.f;
#pragma unroll
            for (int nt = 0; nt < 8; ++nt) {
                float p0 = __expf(s[mt][nt][0] - mn_lo);
                float p1 = __expf(s[mt][nt][1] - mn_lo);
                float p2 = __expf(s[mt][nt][2] - mn_hi);
                float p3 = __expf(s[mt][nt][3] - mn_hi);
                s[mt][nt][0] = p0; s[mt][nt][1] = p1;
                s[mt][nt][2] = p2; s[mt][nt][3] = p3;
                sum_lo += p0 + p1;
                sum_hi += p2 + p3;
            }
#pragma unroll
            for (int off = 1; off <= 2; off <<= 1) {
                sum_lo += __shfl_xor_sync(0xffffffffu, sum_lo, off);
                sum_hi += __shfl_xor_sync(0xffffffffu, sum_hi, off);
            }
            lr[mt][0] = lr[mt][0] * fac_lo + sum_lo;
            lr[mt][1] = lr[mt][1] * fac_hi + sum_hi;
            mr[mt][0] = mn_lo;
            mr[mt][1] = mn_hi;

#pragma unroll
            for (int nt = 0; nt < 8; ++nt) {
                o[mt][nt][0] *= fac_lo; o[mt][nt][1] *= fac_lo;
                o[mt][nt][2] *= fac_hi; o[mt][nt][3] *= fac_hi;
            }

            // write P fragments to smem (warp-private rows, overlaid on Qs)
#pragma unroll
            for (int nt = 0; nt < 8; ++nt) {
                int r = m0 + mt * 16 + qr;
                int c = nt * 8 + 2 * qc;
                QsPs[r * FPQ + c]           = f2t(s[mt][nt][0]);
                QsPs[r * FPQ + c + 1]       = f2t(s[mt][nt][1]);
                QsPs[(r + 8) * FPQ + c]     = f2t(s[mt][nt][2]);
                QsPs[(r + 8) * FPQ + c + 1] = f2t(s[mt][nt][3]);
            }
        }
        __syncwarp();

        // ---- O += P V ----
#pragma unroll
        for (int ks = 0; ks < 8; ++ks) {
            const int k0 = ks * 8;
            unsigned a[2][4];
#pragma unroll
            for (int mt = 0; mt < 2; ++mt) {
                int m = m0 + mt * 16;
                a[mt][0] = QsPs[(m + qr) * FPQ + k0 + qc];
                a[mt][1] = QsPs[(m + 8 + qr) * FPQ + k0 + qc];
                a[mt][2] = QsPs[(m + qr) * FPQ + k0 + 4 + qc];
                a[mt][3] = QsPs[(m + 8 + qr) * FPQ + k0 + 4 + qc];
            }
#pragma unroll
            for (int nt = 0; nt < 8; ++nt) {
                unsigned b0 = Vs[(k0 + qc) * FPV + nt * 8 + qr];
                unsigned b1 = Vs[(k0 + 4 + qc) * FPV + nt * 8 + qr];
#pragma unroll
                for (int mt = 0; mt < 2; ++mt)
                    mma_tf32(o[mt][nt], a[mt][0], a[mt][1], a[mt][2], a[mt][3], b0, b1);
            }
        }
    }

    // ---- normalize + write out ----
#pragma unroll
    for (int mt = 0; mt < 2; ++mt) {
        float inv_lo = 1.f / lr[mt][0];
        float inv_hi = 1.f / lr[mt][1];
#pragma unroll
        for (int nt = 0; nt < 8; ++nt) {
            int row = qbase + m0 + mt * 16 + qr;
            int col = h * D + nt * 8 + 2 * qc;
            *(float2*)&O[(size_t)row * QSTRIDE + col] =
                make_float2(o[mt][nt][0] * inv_lo, o[mt][nt][1] * inv_lo);
            *(float2*)&O[(size_t)(row + 8) * QSTRIDE + col] =
                make_float2(o[mt][nt][2] * inv_hi, o[mt][nt][3] * inv_hi);
        }
    }
}

// ---------------- launch ---------------------------------------------------
extern "C" void kernel_launch(void* const* d_in, const int* in_sizes, int n_in,
                              void* d_out, int out_size) {
    const float* x  = (const float*)d_in[0];
    const float* fc = (const float*)d_in[1];
    const float* Wq = (const float*)d_in[3];
    const float* Wk = (const float*)d_in[4];
    const float* Wv = (const float*)d_in[5];
    const float* Wo = (const float*)d_in[6];
    float* out = (float*)d_out;

    float *Q, *K, *V, *A;
    cudaGetSymbolAddress((void**)&Q, g_Q);
    cudaGetSymbolAddress((void**)&K, g_K);
    cudaGetSymbolAddress((void**)&V, g_V);
    cudaGetSymbolAddress((void**)&A, g_A);

    cudaFuncSetAttribute(qkv_gemm_kernel,
                         cudaFuncAttributeMaxDynamicSharedMemorySize, GEMM_SMEM_BYTES);
    cudaFuncSetAttribute(tgemm_kernel,
                         cudaFuncAttributeMaxDynamicSharedMemorySize, GEMM_SMEM_BYTES);
    cudaFuncSetAttribute(flash_tc_kernel,
                         cudaFuncAttributeMaxDynamicSharedMemorySize, FA_SMEM_BYTES);

    // fused QKV projection + RoPE (Q,K only)
    qkv_gemm_kernel<<<dim3(NTOT / 128, S / 128), 128, GEMM_SMEM_BYTES>>>(
        x, Wq, Wk, Wv, fc, Q, K, V);

    // causal GQA flash attention (hoisted Q fragments, Ps overlaid on Qs)
    flash_tc_kernel<<<dim3(S / 128, HQ), 128, FA_SMEM_BYTES>>>(Q, K, V, A);

    // output projection
    tgemm_kernel<<<dim3(E / 128, S / 128), 128, GEMM_SMEM_BYTES>>>(A, Wo, out, S, E, E);
}